// round 1
// baseline (speedup 1.0000x reference)
#include <cuda_runtime.h>
#include <cstdint>

#define NPIX   262144      // 512*512
#define HI     128
#define WI     128
#define CCH    64
#define NSTR   640         // padded N for layer-3 output (576 -> 640)

// ---------------- scratch (device globals; no allocation) ----------------
__device__ float g_H2 [ (size_t)NPIX * 256 ];   // relu(layer2) activations, row-major [pix][256]
__device__ float g_W2T[ 64 * 256 ];             // W2 transposed: [k][n]
__device__ float g_W3T[ 256 * NSTR ];           // W3 transposed + zero-padded: [k][n]
__device__ float g_B3P[ NSTR ];                 // b3 zero-padded
__device__ float g_W3O[ (size_t)NPIX * NSTR ];  // layer-3 logits, [pix][640]
__device__ float g_XT [ 2 * HI * WI * CCH ];    // x transposed to [b][y][x][c]

// ---------------- prep: weight transposes ----------------
__global__ void prep_w(const float* __restrict__ W2, const float* __restrict__ W3,
                       const float* __restrict__ b3) {
    int idx = blockIdx.x * blockDim.x + threadIdx.x;
    if (idx < 64 * 256) {            // W2T[k][n] = W2[n][k]
        int k = idx / 256, n = idx % 256;
        g_W2T[idx] = W2[n * 64 + k];
    }
    if (idx < 256 * NSTR) {          // W3T[k][n] = W3[n][k], zero pad n>=576
        int k = idx / NSTR, n = idx % NSTR;
        g_W3T[idx] = (n < 576) ? W3[n * 256 + k] : 0.f;
    }
    if (idx < NSTR) g_B3P[idx] = (idx < 576) ? b3[idx] : 0.f;
}

// ---------------- prep: x NCHW -> NHWC ----------------
__global__ void prep_x(const float* __restrict__ x) {
    int o = blockIdx.x * blockDim.x + threadIdx.x;
    if (o >= 2 * HI * WI * CCH) return;
    int c = o & 63;
    int t = o >> 6;
    int xx = t & (WI - 1); t >>= 7;
    int y  = t & (HI - 1); t >>= 7;
    int b  = t;
    g_XT[o] = x[(((b * CCH + c) * HI + y) * WI) + xx];
}

// ---------------- K1: pose -> h1 (relu) -> h2 (relu), 32 pixels/block ----------------
__global__ __launch_bounds__(256) void k1(const float* __restrict__ pose,
                                          const float* __restrict__ W1,
                                          const float* __restrict__ b1,
                                          const float* __restrict__ b2) {
    __shared__ __align__(16) float h1s[64][32];   // [k][px]
    __shared__ float ps[3][32];
    int tid = threadIdx.x;
    int px0 = blockIdx.x * 32;

    if (tid < 96) {
        int j = tid / 32, i = tid % 32;
        ps[j][i] = pose[j * NPIX + px0 + i];
    }
    __syncthreads();

    int i = tid & 31, cg = tid >> 5;
    float p0 = ps[0][i], p1 = ps[1][i], p2 = ps[2][i];
#pragma unroll
    for (int j = 0; j < 8; j++) {
        int c = cg * 8 + j;
        float v = W1[c * 3 + 0] * p0 + W1[c * 3 + 1] * p1 + W1[c * 3 + 2] * p2 + b1[c];
        h1s[c][i] = fmaxf(v, 0.f);
    }
    __syncthreads();

    int n = tid;                       // output channel 0..255
    float acc[32];
    float bb = b2[n];
#pragma unroll
    for (int q = 0; q < 32; q++) acc[q] = bb;

#pragma unroll 4
    for (int k = 0; k < 64; k++) {
        float w = g_W2T[k * 256 + n];
        const float4* h4 = (const float4*)&h1s[k][0];
#pragma unroll
        for (int q = 0; q < 8; q++) {
            float4 h = h4[q];
            acc[4 * q + 0] += w * h.x;
            acc[4 * q + 1] += w * h.y;
            acc[4 * q + 2] += w * h.z;
            acc[4 * q + 3] += w * h.w;
        }
    }
#pragma unroll
    for (int q = 0; q < 32; q++)
        g_H2[(size_t)(px0 + q) * 256 + n] = fmaxf(acc[q], 0.f);
}

// ---------------- K2: SGEMM  W3O = H2[262144x256] * W3T[256x640] + b3 ----------------
#define BM 128
#define BN 128
#define BK 8
__global__ __launch_bounds__(256) void k2() {
    __shared__ __align__(16) float As[2][BK][BM];
    __shared__ __align__(16) float Bs[2][BK][BN];

    int tid = threadIdx.x;
    int n0 = blockIdx.x * BN;   // 5 tiles
    int m0 = blockIdx.y * BM;   // 2048 tiles

    const float* A = g_H2;
    const float* B = g_W3T;

    int arow = tid >> 1, acol = (tid & 1) * 4;   // A tile: 128 rows x 8 k
    int brow = tid >> 5, bcol = (tid & 31) * 4;  // B tile: 8 k x 128 n

    float4 a4 = *(const float4*)&A[(size_t)(m0 + arow) * 256 + acol];
    float4 b4 = *(const float4*)&B[(size_t)brow * NSTR + n0 + bcol];
    As[0][acol + 0][arow] = a4.x; As[0][acol + 1][arow] = a4.y;
    As[0][acol + 2][arow] = a4.z; As[0][acol + 3][arow] = a4.w;
    *(float4*)&Bs[0][brow][bcol] = b4;
    __syncthreads();

    float acc[8][8] = {};
    int tx = tid & 15, ty = tid >> 4;
    int cur = 0;

    for (int kc = 0; kc < 32; kc++) {
        if (kc < 31) {
            int kb = (kc + 1) * BK;
            a4 = *(const float4*)&A[(size_t)(m0 + arow) * 256 + kb + acol];
            b4 = *(const float4*)&B[(size_t)(kb + brow) * NSTR + n0 + bcol];
        }
#pragma unroll
        for (int k = 0; k < BK; k++) {
            float4 a0 = *(const float4*)&As[cur][k][tx * 4];
            float4 a1 = *(const float4*)&As[cur][k][tx * 4 + 64];
            float4 v0 = *(const float4*)&Bs[cur][k][ty * 4];
            float4 v1 = *(const float4*)&Bs[cur][k][ty * 4 + 64];
            float am[8] = {a0.x, a0.y, a0.z, a0.w, a1.x, a1.y, a1.z, a1.w};
            float bn[8] = {v0.x, v0.y, v0.z, v0.w, v1.x, v1.y, v1.z, v1.w};
#pragma unroll
            for (int mi = 0; mi < 8; mi++)
#pragma unroll
                for (int ni = 0; ni < 8; ni++)
                    acc[mi][ni] += am[mi] * bn[ni];
        }
        if (kc < 31) {
            int nxt = cur ^ 1;
            As[nxt][acol + 0][arow] = a4.x; As[nxt][acol + 1][arow] = a4.y;
            As[nxt][acol + 2][arow] = a4.z; As[nxt][acol + 3][arow] = a4.w;
            *(float4*)&Bs[nxt][brow][bcol] = b4;
            __syncthreads();
            cur = nxt;
        }
    }

    // epilogue: + bias, store (padded region stored but never read)
    float bias[8];
#pragma unroll
    for (int ni = 0; ni < 8; ni++) {
        int nl = ty * 4 + ((ni < 4) ? ni : 64 + ni - 4);
        bias[ni] = g_B3P[n0 + nl];
    }
#pragma unroll
    for (int mi = 0; mi < 8; mi++) {
        int m = m0 + tx * 4 + ((mi < 4) ? mi : 64 + mi - 4);
        float4 s0, s1;
        s0.x = acc[mi][0] + bias[0]; s0.y = acc[mi][1] + bias[1];
        s0.z = acc[mi][2] + bias[2]; s0.w = acc[mi][3] + bias[3];
        s1.x = acc[mi][4] + bias[4]; s1.y = acc[mi][5] + bias[5];
        s1.z = acc[mi][6] + bias[6]; s1.w = acc[mi][7] + bias[7];
        *(float4*)&g_W3O[(size_t)m * NSTR + n0 + ty * 4]      = s0;
        *(float4*)&g_W3O[(size_t)m * NSTR + n0 + ty * 4 + 64] = s1;
    }
}

// ---------------- K3: softmax(9) + 3x3 gather + output ----------------
__global__ __launch_bounds__(256) void k3(const int* __restrict__ mY,
                                          const int* __restrict__ mX,
                                          float* __restrict__ out) {
    int tid = threadIdx.x;
    int i = tid & 31, cg = tid >> 5;      // i: pixel within block (coalesced), cg: channel group
    int px = blockIdx.x * 32 + i;
    int Y = mY[px], X = mX[px];

    const float* wrow = &g_W3O[(size_t)px * NSTR + cg * 72];  // 8 channels * 9 taps

#pragma unroll 1
    for (int cl = 0; cl < 8; cl++) {
        int c = cg * 8 + cl;
        float w[9];
#pragma unroll
        for (int j = 0; j < 9; j++) w[j] = wrow[cl * 9 + j];
        float mx = w[0];
#pragma unroll
        for (int j = 1; j < 9; j++) mx = fmaxf(mx, w[j]);
        float sw[9], s = 0.f;
#pragma unroll
        for (int j = 0; j < 9; j++) { sw[j] = expf(w[j] - mx); s += sw[j]; }
        float inv = 1.f / s;

#pragma unroll
        for (int b = 0; b < 2; b++) {
            float acc = 0.f;
#pragma unroll
            for (int j = 0; j < 9; j++) {
                int yy = Y + j / 3 - 1;
                int xx = X + j % 3 - 1;
                float g = 0.f;
                if (yy >= 0 && yy < HI && xx >= 0 && xx < WI)
                    g = g_XT[(size_t)(((b * HI + yy) * WI + xx)) * CCH + c];
                acc += sw[j] * g;
            }
            out[(size_t)(b * CCH + c) * NPIX + px] = acc * inv;
        }
    }
}

// ---------------- launch ----------------
extern "C" void kernel_launch(void* const* d_in, const int* in_sizes, int n_in,
                              void* d_out, int out_size) {
    const float* x    = (const float*)d_in[0];
    const float* pose = (const float*)d_in[1];
    const float* W1   = (const float*)d_in[2];
    const float* b1   = (const float*)d_in[3];
    const float* W2   = (const float*)d_in[4];
    const float* b2   = (const float*)d_in[5];
    const float* W3   = (const float*)d_in[6];
    const float* b3   = (const float*)d_in[7];
    const int*   mY   = (const int*)d_in[8];
    const int*   mX   = (const int*)d_in[9];
    float* out = (float*)d_out;

    prep_w<<<(256 * NSTR + 255) / 256, 256>>>(W2, W3, b3);
    prep_x<<<(2 * HI * WI * CCH + 255) / 256, 256>>>(x);
    k1<<<NPIX / 32, 256>>>(pose, W1, b1, b2);
    dim3 g2(NSTR / BN, NPIX / BM);
    k2<<<g2, 256>>>();
    k3<<<NPIX / 32, 256>>>(mY, mX, out);
}

// round 3
// speedup vs baseline: 1.4121x; 1.4121x over previous
#include <cuda_runtime.h>
#include <cuda_bf16.h>
#include <cstdint>

#define NPIX   262144      // 512*512
#define HI     128
#define WI     128
#define CCH    64
#define NOUT   576         // C*KS*KS

// ---------------- scratch (device globals; no allocation) ----------------
__device__ __nv_bfloat16 g_H2h[(size_t)NPIX * 256];  // bf16 hi of relu(layer2), [pix][256]
__device__ __nv_bfloat16 g_H2l[(size_t)NPIX * 256];  // bf16 lo residual
__device__ __nv_bfloat16 g_W3h[NOUT * 256];          // bf16 hi of W3, native [n][k]
__device__ __nv_bfloat16 g_W3l[NOUT * 256];          // bf16 lo residual
__device__ float g_W2T[64 * 256];                    // W2 transposed: [k][n]
__device__ float g_W3O[(size_t)NPIX * NOUT];         // layer-3 logits, [pix][576]
__device__ float g_XT [2 * HI * WI * CCH];           // x transposed to [b][y][x][c]

__device__ __forceinline__ uint32_t smem_u32(const void* p) {
    uint32_t a;
    asm("{ .reg .u64 t; cvta.to.shared.u64 t, %1; cvt.u32.u64 %0, t; }" : "=r"(a) : "l"(p));
    return a;
}

// ---------------- prep: weight transforms + bf16 split ----------------
__global__ void prep_w(const float* __restrict__ W2, const float* __restrict__ W3) {
    int idx = blockIdx.x * blockDim.x + threadIdx.x;
    if (idx < 64 * 256) {            // W2T[k][n] = W2[n][k]
        int k = idx / 256, n = idx % 256;
        g_W2T[idx] = W2[n * 64 + k];
    }
    if (idx < NOUT * 256) {          // split W3 (native [n][k] layout kept)
        float v = W3[idx];
        __nv_bfloat16 h = __float2bfloat16(v);
        g_W3h[idx] = h;
        g_W3l[idx] = __float2bfloat16(v - __bfloat162float(h));
    }
}

// ---------------- prep: x NCHW -> NHWC ----------------
__global__ void prep_x(const float* __restrict__ x) {
    int o = blockIdx.x * blockDim.x + threadIdx.x;
    if (o >= 2 * HI * WI * CCH) return;
    int c = o & 63;
    int t = o >> 6;
    int xx = t & (WI - 1); t >>= 7;
    int y  = t & (HI - 1); t >>= 7;
    int b  = t;
    g_XT[o] = x[(((b * CCH + c) * HI + y) * WI) + xx];
}

// ---------------- K1: pose -> h1 (relu) -> h2 (relu) -> bf16 split ----------------
__global__ __launch_bounds__(256) void k1(const float* __restrict__ pose,
                                          const float* __restrict__ W1,
                                          const float* __restrict__ b1,
                                          const float* __restrict__ b2) {
    __shared__ __align__(16) float h1s[64][32];
    __shared__ float ps[3][32];
    int tid = threadIdx.x;
    int px0 = blockIdx.x * 32;

    if (tid < 96) {
        int j = tid / 32, i = tid % 32;
        ps[j][i] = pose[j * NPIX + px0 + i];
    }
    __syncthreads();

    int i = tid & 31, cg = tid >> 5;
    float p0 = ps[0][i], p1 = ps[1][i], p2 = ps[2][i];
#pragma unroll
    for (int j = 0; j < 8; j++) {
        int c = cg * 8 + j;
        float v = W1[c * 3 + 0] * p0 + W1[c * 3 + 1] * p1 + W1[c * 3 + 2] * p2 + b1[c];
        h1s[c][i] = fmaxf(v, 0.f);
    }
    __syncthreads();

    int n = tid;
    float acc[32];
    float bb = b2[n];
#pragma unroll
    for (int q = 0; q < 32; q++) acc[q] = bb;

#pragma unroll 4
    for (int k = 0; k < 64; k++) {
        float w = g_W2T[k * 256 + n];
        const float4* h4 = (const float4*)&h1s[k][0];
#pragma unroll
        for (int q = 0; q < 8; q++) {
            float4 h = h4[q];
            acc[4 * q + 0] += w * h.x;
            acc[4 * q + 1] += w * h.y;
            acc[4 * q + 2] += w * h.z;
            acc[4 * q + 3] += w * h.w;
        }
    }
#pragma unroll
    for (int q = 0; q < 32; q++) {
        float v = fmaxf(acc[q], 0.f);
        __nv_bfloat16 h = __float2bfloat16(v);
        size_t idx = (size_t)(px0 + q) * 256 + n;
        g_H2h[idx] = h;
        g_H2l[idx] = __float2bfloat16(v - __bfloat162float(h));
    }
}

// ---------------- K2: bf16-split HMMA GEMM ----------------
// W3O[262144 x 576] = H2[262144 x 256] * W3^T + b3, via
// D = Ah*Bh + Ah*Bl + Al*Bh   (virtual K' = 3*256 = 768)
// CTA: 256 thr, tile M=128 x N=64; warp tile 32x32; K-chunk 64; 4-stage cp.async.
#define KC2      64
#define NCHUNK2  12
#define A_ST     16384                    // 128 rows * 128B (64 bf16)
#define B_ST     8192                     // 64 rows * 128B
#define STAGE2   (A_ST + B_ST)            // 24576
#define NSTG     4
#define K2_SMEM  (NSTG * STAGE2)          // 98304

#define CP16(dst, src) \
    asm volatile("cp.async.cg.shared.global [%0], [%1], 16;" :: "r"(dst), "l"(src))
#define CP_COMMIT() asm volatile("cp.async.commit_group;")
#define CP_WAIT2()  asm volatile("cp.async.wait_group 2;")

#define LDSM_X4(r0, r1, r2, r3, a) \
    asm volatile("ldmatrix.sync.aligned.m8n8.x4.shared.b16 {%0,%1,%2,%3}, [%4];" \
        : "=r"(r0), "=r"(r1), "=r"(r2), "=r"(r3) : "r"(a))

#define MMA16816(d, a0, a1, a2, a3, b0, b1) \
    asm volatile("mma.sync.aligned.m16n8k16.row.col.f32.bf16.bf16.f32 " \
        "{%0,%1,%2,%3}, {%4,%5,%6,%7}, {%8,%9}, {%0,%1,%2,%3};" \
        : "+f"((d)[0]), "+f"((d)[1]), "+f"((d)[2]), "+f"((d)[3]) \
        : "r"(a0), "r"(a1), "r"(a2), "r"(a3), "r"(b0), "r"(b1))

__global__ __launch_bounds__(256) void k2(const float* __restrict__ b3) {
    extern __shared__ __align__(128) char smem[];
    const uint32_t sbase = smem_u32(smem);
    const int tid = threadIdx.x;
    const int wid = tid >> 5, lane = tid & 31;

    const int n0 = blockIdx.x * 64;
    const int m0 = blockIdx.y * 128;

    // per-thread cp.async geometry (4 A ops + 2 B ops per chunk)
    int aRow[4], aDst[4], bRow[2], bDst[2];
#pragma unroll
    for (int i = 0; i < 4; i++) {
        int o = tid + i * 256;
        int row = o >> 3, grp = o & 7;
        aRow[i] = row;
        aDst[i] = row * 128 + ((grp * 16) ^ ((row & 7) << 4));
    }
#pragma unroll
    for (int i = 0; i < 2; i++) {
        int o = tid + i * 256;
        int row = o >> 3, grp = o & 7;
        bRow[i] = row;
        bDst[i] = A_ST + row * 128 + ((grp * 16) ^ ((row & 7) << 4));
    }
    const int aGrp0 = (tid & 7) * 8;   // bf16 elem offset of this thread's 16B chunk

    // prefetch stages 0..2
#pragma unroll
    for (int c = 0; c < NSTG - 1; c++) {
        int r = c >> 2, kb = (c & 3) * KC2;
        const __nv_bfloat16* As = (r < 2) ? g_H2h : g_H2l;
        const __nv_bfloat16* Bs = (r == 1) ? g_W3l : g_W3h;
        uint32_t sb = sbase + c * STAGE2;
#pragma unroll
        for (int i = 0; i < 4; i++)
            CP16(sb + aDst[i], As + (size_t)(m0 + aRow[i]) * 256 + kb + aGrp0);
#pragma unroll
        for (int i = 0; i < 2; i++)
            CP16(sb + bDst[i], Bs + (size_t)(n0 + bRow[i]) * 256 + kb + aGrp0);
        CP_COMMIT();
    }

    // warp tiling + ldmatrix lane addressing
    const int warpM = (wid >> 1) * 32;
    const int warpN = (wid & 1) * 32;
    const int q = lane >> 3, r8 = lane & 7;
    const int xm = r8 << 4;
    // A: reg pair order (rows q&1, k-group q>>1)
    const int aRowL = warpM + ((q & 1) << 3) + r8;
    const int aKofs = (q >> 1) << 4;
    // B: (n-half q>>1, k-group q&1)
    const int bRowL = warpN + ((q >> 1) << 3) + r8;
    const int bKofs = (q & 1) << 4;

    float acc[2][4][4] = {};

    for (int c = 0; c < NCHUNK2; c++) {
        // issue chunk c+3
        int cf = c + NSTG - 1;
        if (cf < NCHUNK2) {
            int r = cf >> 2, kb = (cf & 3) * KC2;
            const __nv_bfloat16* As = (r < 2) ? g_H2h : g_H2l;
            const __nv_bfloat16* Bs = (r == 1) ? g_W3l : g_W3h;
            uint32_t sb = sbase + (cf & (NSTG - 1)) * STAGE2;
#pragma unroll
            for (int i = 0; i < 4; i++)
                CP16(sb + aDst[i], As + (size_t)(m0 + aRow[i]) * 256 + kb + aGrp0);
#pragma unroll
            for (int i = 0; i < 2; i++)
                CP16(sb + bDst[i], Bs + (size_t)(n0 + bRow[i]) * 256 + kb + aGrp0);
        }
        CP_COMMIT();
        CP_WAIT2();
        __syncthreads();

        uint32_t Sb = sbase + (c & (NSTG - 1)) * STAGE2;
        uint32_t Bb = Sb + A_ST;

#pragma unroll
        for (int ks = 0; ks < 4; ks++) {
            uint32_t a[8], b[8];
            int kbyte = ks * 32;
            LDSM_X4(a[0], a[1], a[2], a[3], Sb + aRowL * 128        + ((kbyte + aKofs) ^ xm));
            LDSM_X4(a[4], a[5], a[6], a[7], Sb + (aRowL + 16) * 128 + ((kbyte + aKofs) ^ xm));
            LDSM_X4(b[0], b[1], b[2], b[3], Bb + bRowL * 128        + ((kbyte + bKofs) ^ xm));
            LDSM_X4(b[4], b[5], b[6], b[7], Bb + (bRowL + 16) * 128 + ((kbyte + bKofs) ^ xm));
#pragma unroll
            for (int mi = 0; mi < 2; mi++)
#pragma unroll
                for (int ni = 0; ni < 4; ni++)
                    MMA16816(acc[mi][ni], a[mi * 4 + 0], a[mi * 4 + 1], a[mi * 4 + 2], a[mi * 4 + 3],
                             b[ni * 2 + 0], b[ni * 2 + 1]);
        }
        __syncthreads();
    }

    // epilogue: + bias, store fp32 logits
    const int g = lane >> 2, t = lane & 3;
#pragma unroll
    for (int mi = 0; mi < 2; mi++) {
#pragma unroll
        for (int ni = 0; ni < 4; ni++) {
            int mg = m0 + warpM + mi * 16 + g;
            int nc = n0 + warpN + ni * 8 + 2 * t;
            float2 bv = *(const float2*)&b3[nc];
            float2 s0 = {acc[mi][ni][0] + bv.x, acc[mi][ni][1] + bv.y};
            float2 s1 = {acc[mi][ni][2] + bv.x, acc[mi][ni][3] + bv.y};
            *(float2*)&g_W3O[(size_t)mg * NOUT + nc] = s0;
            *(float2*)&g_W3O[(size_t)(mg + 8) * NOUT + nc] = s1;
        }
    }
}

// ---------------- K3: softmax(9) + 3x3 gather + output ----------------
__global__ __launch_bounds__(256) void k3(const int* __restrict__ mY,
                                          const int* __restrict__ mX,
                                          float* __restrict__ out) {
    int tid = threadIdx.x;
    int i = tid & 31, cg = tid >> 5;
    int px = blockIdx.x * 32 + i;
    int Y = mY[px], X = mX[px];

    const float* wrow = &g_W3O[(size_t)px * NOUT + cg * 72];

#pragma unroll 1
    for (int cl = 0; cl < 8; cl++) {
        int c = cg * 8 + cl;
        float w[9];
#pragma unroll
        for (int j = 0; j < 9; j++) w[j] = wrow[cl * 9 + j];
        float mx = w[0];
#pragma unroll
        for (int j = 1; j < 9; j++) mx = fmaxf(mx, w[j]);
        float sw[9], s = 0.f;
#pragma unroll
        for (int j = 0; j < 9; j++) { sw[j] = expf(w[j] - mx); s += sw[j]; }
        float inv = 1.f / s;

#pragma unroll
        for (int b = 0; b < 2; b++) {
            float acc = 0.f;
#pragma unroll
            for (int j = 0; j < 9; j++) {
                int yy = Y + j / 3 - 1;
                int xx = X + j % 3 - 1;
                float g = 0.f;
                if (yy >= 0 && yy < HI && xx >= 0 && xx < WI)
                    g = g_XT[(size_t)(((b * HI + yy) * WI + xx)) * CCH + c];
                acc += sw[j] * g;
            }
            out[(size_t)(b * CCH + c) * NPIX + px] = acc * inv;
        }
    }
}

// ---------------- launch ----------------
extern "C" void kernel_launch(void* const* d_in, const int* in_sizes, int n_in,
                              void* d_out, int out_size) {
    const float* x    = (const float*)d_in[0];
    const float* pose = (const float*)d_in[1];
    const float* W1   = (const float*)d_in[2];
    const float* b1   = (const float*)d_in[3];
    const float* W2   = (const float*)d_in[4];
    const float* b2   = (const float*)d_in[5];
    const float* W3   = (const float*)d_in[6];
    const float* b3   = (const float*)d_in[7];
    const int*   mY   = (const int*)d_in[8];
    const int*   mX   = (const int*)d_in[9];
    float* out = (float*)d_out;

    cudaFuncSetAttribute(k2, cudaFuncAttributeMaxDynamicSharedMemorySize, K2_SMEM);

    prep_w<<<(NOUT * 256 + 255) / 256, 256>>>(W2, W3);
    prep_x<<<(2 * HI * WI * CCH + 255) / 256, 256>>>(x);
    k1<<<NPIX / 32, 256>>>(pose, W1, b1, b2);
    dim3 g2(NOUT / 64, NPIX / 128);
    k2<<<g2, 256, K2_SMEM>>>(b3);
    k3<<<NPIX / 32, 256>>>(mY, mX, out);
}

// round 4
// speedup vs baseline: 3.1414x; 2.2246x over previous
#include <cuda_runtime.h>
#include <cuda_bf16.h>
#include <cstdint>

#define NPIX   262144      // 512*512
#define HI     128
#define WI     128
#define CCH    64
#define NOUT   576         // C*KS*KS

// ---------------- scratch (device globals; no allocation) ----------------
__device__ __nv_bfloat16 g_H2h[(size_t)NPIX * 256];  // bf16 hi of relu(layer2), [pix][256]
__device__ __nv_bfloat16 g_H2l[(size_t)NPIX * 256];  // bf16 lo residual
__device__ __nv_bfloat16 g_W3h[NOUT * 256];          // bf16 hi of W3, native [n][k]
__device__ __nv_bfloat16 g_W3l[NOUT * 256];          // bf16 lo residual
__device__ float g_W2T[64 * 256];                    // W2 transposed: [k][n]
__device__ float g_W3O[(size_t)NPIX * NOUT];         // layer-3 logits, [pix][576]
__device__ float g_XT [2 * HI * WI * CCH];           // x transposed to [b][y][x][c]

__device__ __forceinline__ uint32_t smem_u32(const void* p) {
    uint32_t a;
    asm("{ .reg .u64 t; cvta.to.shared.u64 t, %1; cvt.u32.u64 %0, t; }" : "=r"(a) : "l"(p));
    return a;
}

// ---------------- prep: weight transforms + bf16 split ----------------
__global__ void prep_w(const float* __restrict__ W2, const float* __restrict__ W3) {
    int idx = blockIdx.x * blockDim.x + threadIdx.x;
    if (idx < 64 * 256) {            // W2T[k][n] = W2[n][k]
        int k = idx / 256, n = idx % 256;
        g_W2T[idx] = W2[n * 64 + k];
    }
    if (idx < NOUT * 256) {          // split W3 (native [n][k] layout kept)
        float v = W3[idx];
        __nv_bfloat16 h = __float2bfloat16(v);
        g_W3h[idx] = h;
        g_W3l[idx] = __float2bfloat16(v - __bfloat162float(h));
    }
}

// ---------------- prep: x NCHW -> NHWC ----------------
__global__ void prep_x(const float* __restrict__ x) {
    int o = blockIdx.x * blockDim.x + threadIdx.x;
    if (o >= 2 * HI * WI * CCH) return;
    int c = o & 63;
    int t = o >> 6;
    int xx = t & (WI - 1); t >>= 7;
    int y  = t & (HI - 1); t >>= 7;
    int b  = t;
    g_XT[o] = x[(((b * CCH + c) * HI + y) * WI) + xx];
}

// ---------------- K1: pose -> h1 -> h2 -> bf16 split (128 px/block, 8x8 tiles) ----------------
#define K1_SMEM ((16384 + 8192) * 4)    // W2s[64][256] + h1s[64][128]
__global__ __launch_bounds__(512) void k1(const float* __restrict__ pose,
                                          const float* __restrict__ W1,
                                          const float* __restrict__ b1,
                                          const float* __restrict__ b2) {
    extern __shared__ __align__(16) float sm1[];
    float* W2s = sm1;             // 64 x 256
    float* h1s = sm1 + 16384;     // 64 x 128
    const int tid = threadIdx.x;
    const int px0g = blockIdx.x * 128;

    // load W2T into smem (straight copy, 4096 float4)
#pragma unroll
    for (int j = 0; j < 8; j++) {
        int i = tid + j * 512;
        ((float4*)W2s)[i] = ((const float4*)g_W2T)[i];
    }
    // compute h1 = relu(W1*pose + b1): 8192 items
#pragma unroll
    for (int j = 0; j < 16; j++) {
        int idx = tid + j * 512;
        int c = idx >> 7, px = idx & 127;
        float p0 = pose[0 * NPIX + px0g + px];
        float p1 = pose[1 * NPIX + px0g + px];
        float p2 = pose[2 * NPIX + px0g + px];
        float v = W1[c * 3 + 0] * p0 + W1[c * 3 + 1] * p1 + W1[c * 3 + 2] * p2 + b1[c];
        h1s[c * 128 + px] = fmaxf(v, 0.f);
    }
    __syncthreads();

    // GEMM: [128 px][256 n] = h1s^T[128x64] * W2s[64x256]
    const int tx = tid & 31;          // n0 = tx*8
    const int ty = tid >> 5;          // px0 = ty*8
    const int n0 = tx * 8, p0 = ty * 8;

    float acc[8][8];
    float bv[8];
#pragma unroll
    for (int j = 0; j < 8; j++) bv[j] = b2[n0 + j];
#pragma unroll
    for (int i = 0; i < 8; i++)
#pragma unroll
        for (int j = 0; j < 8; j++) acc[i][j] = bv[j];

#pragma unroll 8
    for (int k = 0; k < 64; k++) {
        float4 a0 = *(const float4*)&h1s[k * 128 + p0];
        float4 a1 = *(const float4*)&h1s[k * 128 + p0 + 4];
        float4 w0 = *(const float4*)&W2s[k * 256 + n0];
        float4 w1 = *(const float4*)&W2s[k * 256 + n0 + 4];
        float am[8] = {a0.x, a0.y, a0.z, a0.w, a1.x, a1.y, a1.z, a1.w};
        float wn[8] = {w0.x, w0.y, w0.z, w0.w, w1.x, w1.y, w1.z, w1.w};
#pragma unroll
        for (int i = 0; i < 8; i++)
#pragma unroll
            for (int j = 0; j < 8; j++) acc[i][j] += am[i] * wn[j];
    }

    // relu + bf16 split + coalesced 16B stores
#pragma unroll
    for (int i = 0; i < 8; i++) {
        __nv_bfloat16 hi8[8], lo8[8];
#pragma unroll
        for (int j = 0; j < 8; j++) {
            float v = fmaxf(acc[i][j], 0.f);
            __nv_bfloat16 h = __float2bfloat16(v);
            hi8[j] = h;
            lo8[j] = __float2bfloat16(v - __bfloat162float(h));
        }
        size_t base = (size_t)(px0g + p0 + i) * 256 + n0;
        *(uint4*)&g_H2h[base] = *(const uint4*)hi8;
        *(uint4*)&g_H2l[base] = *(const uint4*)lo8;
    }
}

// ---------------- K2: bf16-split HMMA GEMM (unchanged) ----------------
#define KC2      64
#define NCHUNK2  12
#define A_ST     16384
#define B_ST     8192
#define STAGE2   (A_ST + B_ST)
#define NSTG     4
#define K2_SMEM  (NSTG * STAGE2)

#define CP16(dst, src) \
    asm volatile("cp.async.cg.shared.global [%0], [%1], 16;" :: "r"(dst), "l"(src))
#define CP_COMMIT() asm volatile("cp.async.commit_group;")
#define CP_WAIT2()  asm volatile("cp.async.wait_group 2;")

#define LDSM_X4(r0, r1, r2, r3, a) \
    asm volatile("ldmatrix.sync.aligned.m8n8.x4.shared.b16 {%0,%1,%2,%3}, [%4];" \
        : "=r"(r0), "=r"(r1), "=r"(r2), "=r"(r3) : "r"(a))

#define MMA16816(d, a0, a1, a2, a3, b0, b1) \
    asm volatile("mma.sync.aligned.m16n8k16.row.col.f32.bf16.bf16.f32 " \
        "{%0,%1,%2,%3}, {%4,%5,%6,%7}, {%8,%9}, {%0,%1,%2,%3};" \
        : "+f"((d)[0]), "+f"((d)[1]), "+f"((d)[2]), "+f"((d)[3]) \
        : "r"(a0), "r"(a1), "r"(a2), "r"(a3), "r"(b0), "r"(b1))

__global__ __launch_bounds__(256) void k2(const float* __restrict__ b3) {
    extern __shared__ __align__(128) char smem[];
    const uint32_t sbase = smem_u32(smem);
    const int tid = threadIdx.x;
    const int wid = tid >> 5, lane = tid & 31;

    const int n0 = blockIdx.x * 64;
    const int m0 = blockIdx.y * 128;

    int aRow[4], aDst[4], bRow[2], bDst[2];
#pragma unroll
    for (int i = 0; i < 4; i++) {
        int o = tid + i * 256;
        int row = o >> 3, grp = o & 7;
        aRow[i] = row;
        aDst[i] = row * 128 + ((grp * 16) ^ ((row & 7) << 4));
    }
#pragma unroll
    for (int i = 0; i < 2; i++) {
        int o = tid + i * 256;
        int row = o >> 3, grp = o & 7;
        bRow[i] = row;
        bDst[i] = A_ST + row * 128 + ((grp * 16) ^ ((row & 7) << 4));
    }
    const int aGrp0 = (tid & 7) * 8;

#pragma unroll
    for (int c = 0; c < NSTG - 1; c++) {
        int r = c >> 2, kb = (c & 3) * KC2;
        const __nv_bfloat16* As = (r < 2) ? g_H2h : g_H2l;
        const __nv_bfloat16* Bs = (r == 1) ? g_W3l : g_W3h;
        uint32_t sb = sbase + c * STAGE2;
#pragma unroll
        for (int i = 0; i < 4; i++)
            CP16(sb + aDst[i], As + (size_t)(m0 + aRow[i]) * 256 + kb + aGrp0);
#pragma unroll
        for (int i = 0; i < 2; i++)
            CP16(sb + bDst[i], Bs + (size_t)(n0 + bRow[i]) * 256 + kb + aGrp0);
        CP_COMMIT();
    }

    const int warpM = (wid >> 1) * 32;
    const int warpN = (wid & 1) * 32;
    const int q = lane >> 3, r8 = lane & 7;
    const int xm = r8 << 4;
    const int aRowL = warpM + ((q & 1) << 3) + r8;
    const int aKofs = (q >> 1) << 4;
    const int bRowL = warpN + ((q >> 1) << 3) + r8;
    const int bKofs = (q & 1) << 4;

    float acc[2][4][4] = {};

    for (int c = 0; c < NCHUNK2; c++) {
        int cf = c + NSTG - 1;
        if (cf < NCHUNK2) {
            int r = cf >> 2, kb = (cf & 3) * KC2;
            const __nv_bfloat16* As = (r < 2) ? g_H2h : g_H2l;
            const __nv_bfloat16* Bs = (r == 1) ? g_W3l : g_W3h;
            uint32_t sb = sbase + (cf & (NSTG - 1)) * STAGE2;
#pragma unroll
            for (int i = 0; i < 4; i++)
                CP16(sb + aDst[i], As + (size_t)(m0 + aRow[i]) * 256 + kb + aGrp0);
#pragma unroll
            for (int i = 0; i < 2; i++)
                CP16(sb + bDst[i], Bs + (size_t)(n0 + bRow[i]) * 256 + kb + aGrp0);
        }
        CP_COMMIT();
        CP_WAIT2();
        __syncthreads();

        uint32_t Sb = sbase + (c & (NSTG - 1)) * STAGE2;
        uint32_t Bb = Sb + A_ST;

#pragma unroll
        for (int ks = 0; ks < 4; ks++) {
            uint32_t a[8], b[8];
            int kbyte = ks * 32;
            LDSM_X4(a[0], a[1], a[2], a[3], Sb + aRowL * 128        + ((kbyte + aKofs) ^ xm));
            LDSM_X4(a[4], a[5], a[6], a[7], Sb + (aRowL + 16) * 128 + ((kbyte + aKofs) ^ xm));
            LDSM_X4(b[0], b[1], b[2], b[3], Bb + bRowL * 128        + ((kbyte + bKofs) ^ xm));
            LDSM_X4(b[4], b[5], b[6], b[7], Bb + (bRowL + 16) * 128 + ((kbyte + bKofs) ^ xm));
#pragma unroll
            for (int mi = 0; mi < 2; mi++)
#pragma unroll
                for (int ni = 0; ni < 4; ni++)
                    MMA16816(acc[mi][ni], a[mi * 4 + 0], a[mi * 4 + 1], a[mi * 4 + 2], a[mi * 4 + 3],
                             b[ni * 2 + 0], b[ni * 2 + 1]);
        }
        __syncthreads();
    }

    const int g = lane >> 2, t = lane & 3;
#pragma unroll
    for (int mi = 0; mi < 2; mi++) {
#pragma unroll
        for (int ni = 0; ni < 4; ni++) {
            int mg = m0 + warpM + mi * 16 + g;
            int nc = n0 + warpN + ni * 8 + 2 * t;
            float2 bvv = *(const float2*)&b3[nc];
            float2 s0 = {acc[mi][ni][0] + bvv.x, acc[mi][ni][1] + bvv.y};
            float2 s1 = {acc[mi][ni][2] + bvv.x, acc[mi][ni][3] + bvv.y};
            *(float2*)&g_W3O[(size_t)mg * NOUT + nc] = s0;
            *(float2*)&g_W3O[(size_t)(mg + 8) * NOUT + nc] = s1;
        }
    }
}

// ---------------- K3: channel-lane softmax + gather (1 warp = 1 pixel) ----------------
// lane owns channel pair (2*lane, 2*lane+1); gathers are 256B-contiguous per warp.
__global__ __launch_bounds__(256) void k3(const int* __restrict__ mY,
                                          const int* __restrict__ mX,
                                          float* __restrict__ out) {
    __shared__ float so[128 * 33];      // [row=b*64+c][px_local], padded stride 33
    const int tid = threadIdx.x;
    const int wid = tid >> 5, lane = tid & 31;
    const int px0 = blockIdx.x * 32;

#pragma unroll 1
    for (int pi = 0; pi < 4; pi++) {
        int pxl = wid * 4 + pi;
        int px = px0 + pxl;
        int Y = mY[px], X = mX[px];

        // load 18 logits (channels 2*lane, 2*lane+1; 9 taps each)
        const float* wr = g_W3O + (size_t)px * NOUT + lane * 18;
        float w[18];
#pragma unroll
        for (int j = 0; j < 9; j++) {
            float2 v = *(const float2*)(wr + 2 * j);
            w[2 * j] = v.x; w[2 * j + 1] = v.y;
        }
        // softmax per channel
        float sw0[9], sw1[9];
        float m0v = w[0], m1v = w[9];
#pragma unroll
        for (int j = 1; j < 9; j++) { m0v = fmaxf(m0v, w[j]); m1v = fmaxf(m1v, w[9 + j]); }
        float s0 = 0.f, s1 = 0.f;
#pragma unroll
        for (int j = 0; j < 9; j++) {
            sw0[j] = __expf(w[j] - m0v);     s0 += sw0[j];
            sw1[j] = __expf(w[9 + j] - m1v); s1 += sw1[j];
        }
        float inv0 = 1.f / s0, inv1 = 1.f / s1;

        // gather: per (tap, batch) one coalesced 256B warp read
        float a0x = 0.f, a0y = 0.f, a1x = 0.f, a1y = 0.f;
#pragma unroll
        for (int j = 0; j < 9; j++) {
            int yy = Y + j / 3 - 1;
            int xx = X + j % 3 - 1;
            if ((unsigned)yy < HI && (unsigned)xx < WI) {
                const float* base0 = g_XT + (size_t)((0 * HI + yy) * WI + xx) * CCH + 2 * lane;
                const float* base1 = g_XT + (size_t)((1 * HI + yy) * WI + xx) * CCH + 2 * lane;
                float2 gv0 = *(const float2*)base0;
                float2 gv1 = *(const float2*)base1;
                a0x += sw0[j] * gv0.x; a0y += sw1[j] * gv0.y;
                a1x += sw0[j] * gv1.x; a1y += sw1[j] * gv1.y;
            }
        }
        so[(0 * 64 + 2 * lane    ) * 33 + pxl] = a0x * inv0;
        so[(0 * 64 + 2 * lane + 1) * 33 + pxl] = a0y * inv1;
        so[(1 * 64 + 2 * lane    ) * 33 + pxl] = a1x * inv0;
        so[(1 * 64 + 2 * lane + 1) * 33 + pxl] = a1y * inv1;
    }
    __syncthreads();

    // coalesced output write: 128 rows x 32 px
    int row = tid >> 1, half = (tid & 1) * 16;
    float* orow = out + (size_t)row * NPIX + px0 + half;
    const float* srow = so + row * 33 + half;
#pragma unroll
    for (int i = 0; i < 4; i++) {
        float4 v = {srow[4 * i], srow[4 * i + 1], srow[4 * i + 2], srow[4 * i + 3]};
        *(float4*)&orow[4 * i] = v;
    }
}

// ---------------- launch ----------------
extern "C" void kernel_launch(void* const* d_in, const int* in_sizes, int n_in,
                              void* d_out, int out_size) {
    const float* x    = (const float*)d_in[0];
    const float* pose = (const float*)d_in[1];
    const float* W1   = (const float*)d_in[2];
    const float* b1   = (const float*)d_in[3];
    const float* W2   = (const float*)d_in[4];
    const float* b2   = (const float*)d_in[5];
    const float* W3   = (const float*)d_in[6];
    const float* b3   = (const float*)d_in[7];
    const int*   mY   = (const int*)d_in[8];
    const int*   mX   = (const int*)d_in[9];
    float* out = (float*)d_out;

    cudaFuncSetAttribute(k2, cudaFuncAttributeMaxDynamicSharedMemorySize, K2_SMEM);
    cudaFuncSetAttribute(k1, cudaFuncAttributeMaxDynamicSharedMemorySize, K1_SMEM);

    prep_w<<<(NOUT * 256 + 255) / 256, 256>>>(W2, W3);
    prep_x<<<(2 * HI * WI * CCH + 255) / 256, 256>>>(x);
    k1<<<NPIX / 128, 512, K1_SMEM>>>(pose, W1, b1, b2);
    dim3 g2(NOUT / 64, NPIX / 128);
    k2<<<g2, 256, K2_SMEM>>>(b3);
    k3<<<NPIX / 32, 256>>>(mY, mX, out);
}

// round 6
// speedup vs baseline: 3.5356x; 1.1255x over previous
#include <cuda_runtime.h>
#include <cuda_bf16.h>
#include <cstdint>

#define NPIX   262144      // 512*512
#define HI     128
#define WI     128
#define CCH    64
#define NOUT   576         // C*KS*KS

// ---------------- scratch (device globals; no allocation) ----------------
__device__ __nv_bfloat16 g_H2h[(size_t)NPIX * 256];  // bf16 hi of relu(layer2), [pix][256]
__device__ __nv_bfloat16 g_H2l[(size_t)NPIX * 256];  // bf16 lo residual
__device__ __nv_bfloat16 g_W3h[NOUT * 256];          // bf16 hi of W3, native [n][k]
__device__ __nv_bfloat16 g_W3l[NOUT * 256];          // bf16 lo residual
__device__ float g_W2T[64 * 256];                    // W2 transposed: [k][n]
__device__ float g_W3O[(size_t)NPIX * NOUT];         // layer-3 logits, [pix][576]
__device__ float g_XT [2 * HI * WI * CCH];           // x transposed to [b][y][x][c]

__device__ __forceinline__ uint32_t smem_u32(const void* p) {
    uint32_t a;
    asm("{ .reg .u64 t; cvta.to.shared.u64 t, %1; cvt.u32.u64 %0, t; }" : "=r"(a) : "l"(p));
    return a;
}

// ---------------- prep: weight transforms + bf16 split ----------------
__global__ void prep_w(const float* __restrict__ W2, const float* __restrict__ W3) {
    int idx = blockIdx.x * blockDim.x + threadIdx.x;
    if (idx < 64 * 256) {
        int k = idx / 256, n = idx % 256;
        g_W2T[idx] = W2[n * 64 + k];
    }
    if (idx < NOUT * 256) {
        float v = W3[idx];
        __nv_bfloat16 h = __float2bfloat16(v);
        g_W3h[idx] = h;
        g_W3l[idx] = __float2bfloat16(v - __bfloat162float(h));
    }
}

// ---------------- prep: x NCHW -> NHWC ----------------
__global__ void prep_x(const float* __restrict__ x) {
    int o = blockIdx.x * blockDim.x + threadIdx.x;
    if (o >= 2 * HI * WI * CCH) return;
    int c = o & 63;
    int t = o >> 6;
    int xx = t & (WI - 1); t >>= 7;
    int y  = t & (HI - 1); t >>= 7;
    int b  = t;
    g_XT[o] = x[(((b * CCH + c) * HI + y) * WI) + xx];
}

// ---------------- K1: pose -> h1 -> h2 -> bf16 split (128 px/block, 8x8 tiles) ----------------
#define K1_SMEM ((16384 + 8192) * 4)
__global__ __launch_bounds__(512) void k1(const float* __restrict__ pose,
                                          const float* __restrict__ W1,
                                          const float* __restrict__ b1,
                                          const float* __restrict__ b2) {
    extern __shared__ __align__(16) float sm1[];
    float* W2s = sm1;             // 64 x 256
    float* h1s = sm1 + 16384;     // 64 x 128
    const int tid = threadIdx.x;
    const int px0g = blockIdx.x * 128;

#pragma unroll
    for (int j = 0; j < 8; j++) {
        int i = tid + j * 512;
        ((float4*)W2s)[i] = ((const float4*)g_W2T)[i];
    }
#pragma unroll
    for (int j = 0; j < 16; j++) {
        int idx = tid + j * 512;
        int c = idx >> 7, px = idx & 127;
        float p0 = pose[0 * NPIX + px0g + px];
        float p1 = pose[1 * NPIX + px0g + px];
        float p2 = pose[2 * NPIX + px0g + px];
        float v = W1[c * 3 + 0] * p0 + W1[c * 3 + 1] * p1 + W1[c * 3 + 2] * p2 + b1[c];
        h1s[c * 128 + px] = fmaxf(v, 0.f);
    }
    __syncthreads();

    const int tx = tid & 31;
    const int ty = tid >> 5;
    const int n0 = tx * 8, p0 = ty * 8;

    float acc[8][8];
    float bv[8];
#pragma unroll
    for (int j = 0; j < 8; j++) bv[j] = b2[n0 + j];
#pragma unroll
    for (int i = 0; i < 8; i++)
#pragma unroll
        for (int j = 0; j < 8; j++) acc[i][j] = bv[j];

#pragma unroll 8
    for (int k = 0; k < 64; k++) {
        float4 a0 = *(const float4*)&h1s[k * 128 + p0];
        float4 a1 = *(const float4*)&h1s[k * 128 + p0 + 4];
        float4 w0 = *(const float4*)&W2s[k * 256 + n0];
        float4 w1 = *(const float4*)&W2s[k * 256 + n0 + 4];
        float am[8] = {a0.x, a0.y, a0.z, a0.w, a1.x, a1.y, a1.z, a1.w};
        float wn[8] = {w0.x, w0.y, w0.z, w0.w, w1.x, w1.y, w1.z, w1.w};
#pragma unroll
        for (int i = 0; i < 8; i++)
#pragma unroll
            for (int j = 0; j < 8; j++) acc[i][j] += am[i] * wn[j];
    }

#pragma unroll
    for (int i = 0; i < 8; i++) {
        __nv_bfloat16 hi8[8], lo8[8];
#pragma unroll
        for (int j = 0; j < 8; j++) {
            float v = fmaxf(acc[i][j], 0.f);
            __nv_bfloat16 h = __float2bfloat16(v);
            hi8[j] = h;
            lo8[j] = __float2bfloat16(v - __bfloat162float(h));
        }
        size_t base = (size_t)(px0g + p0 + i) * 256 + n0;
        *(uint4*)&g_H2h[base] = *(const uint4*)hi8;
        *(uint4*)&g_H2l[base] = *(const uint4*)lo8;
    }
}

// ---------------- K2: combined-chunk bf16-split HMMA GEMM ----------------
// Per 64-k chunk load Ah,Al,Bh,Bl together; compute AhBh + AhBl + AlBh from one load.
#define KC2      64
#define NCHUNK2  4
#define AH_OFF   0
#define AL_OFF   16384
#define BH_OFF   32768
#define BL_OFF   40960
#define STAGE2   49152
#define K2_SMEM  (2 * STAGE2)     // 98304

#define CP16(dst, src) \
    asm volatile("cp.async.cg.shared.global [%0], [%1], 16;" :: "r"(dst), "l"(src))
#define CP_COMMIT() asm volatile("cp.async.commit_group;")
#define CP_WAITG(n) asm volatile("cp.async.wait_group %0;" :: "n"(n))

#define LDSM_X4(r0, r1, r2, r3, a) \
    asm volatile("ldmatrix.sync.aligned.m8n8.x4.shared.b16 {%0,%1,%2,%3}, [%4];" \
        : "=r"(r0), "=r"(r1), "=r"(r2), "=r"(r3) : "r"(a))

#define MMA16816(d, a0, a1, a2, a3, b0, b1) \
    asm volatile("mma.sync.aligned.m16n8k16.row.col.f32.bf16.bf16.f32 " \
        "{%0,%1,%2,%3}, {%4,%5,%6,%7}, {%8,%9}, {%0,%1,%2,%3};" \
        : "+f"((d)[0]), "+f"((d)[1]), "+f"((d)[2]), "+f"((d)[3]) \
        : "r"(a0), "r"(a1), "r"(a2), "r"(a3), "r"(b0), "r"(b1))

struct K2Geom {
    int aRow[4], aDst[4], bRow[2], bDst[2], grp8;
};

__device__ __forceinline__ void k2_issue(uint32_t sb, int m0, int n0, int kb, const K2Geom& g) {
#pragma unroll
    for (int i = 0; i < 4; i++) {
        size_t asrc = (size_t)(m0 + g.aRow[i]) * 256 + kb + g.grp8;
        CP16(sb + AH_OFF + g.aDst[i], g_H2h + asrc);
        CP16(sb + AL_OFF + g.aDst[i], g_H2l + asrc);
    }
#pragma unroll
    for (int i = 0; i < 2; i++) {
        size_t bsrc = (size_t)(n0 + g.bRow[i]) * 256 + kb + g.grp8;
        CP16(sb + BH_OFF + g.bDst[i], g_W3h + bsrc);
        CP16(sb + BL_OFF + g.bDst[i], g_W3l + bsrc);
    }
    CP_COMMIT();
}

__global__ __launch_bounds__(256) void k2(const float* __restrict__ b3) {
    extern __shared__ __align__(128) char smem[];
    const uint32_t sbase = smem_u32(smem);
    const int tid = threadIdx.x;
    const int wid = tid >> 5, lane = tid & 31;

    const int n0 = blockIdx.x * 64;
    const int m0 = blockIdx.y * 128;

    K2Geom gm;
    gm.grp8 = (tid & 7) * 8;
#pragma unroll
    for (int i = 0; i < 4; i++) {
        int o = tid + i * 256;
        int row = o >> 3, grp = o & 7;
        gm.aRow[i] = row;
        gm.aDst[i] = row * 128 + ((grp * 16) ^ ((row & 7) << 4));
    }
#pragma unroll
    for (int i = 0; i < 2; i++) {
        int o = tid + i * 256;
        int row = o >> 3, grp = o & 7;
        gm.bRow[i] = row;
        gm.bDst[i] = row * 128 + ((grp * 16) ^ ((row & 7) << 4));
    }

    // prefetch chunks 0 and 1
    k2_issue(sbase + 0 * STAGE2, m0, n0, 0 * KC2, gm);
    k2_issue(sbase + 1 * STAGE2, m0, n0, 1 * KC2, gm);

    const int warpM = (wid >> 1) * 32;
    const int warpN = (wid & 1) * 32;
    const int q = lane >> 3, r8 = lane & 7;
    const int xm = r8 << 4;
    const int aRowL = warpM + ((q & 1) << 3) + r8;
    const int aKofs = (q >> 1) << 4;
    const int bRowL = warpN + ((q >> 1) << 3) + r8;
    const int bKofs = (q & 1) << 4;

    float acc[2][4][4] = {};

#pragma unroll 1
    for (int c = 0; c < NCHUNK2; c++) {
        if (c < NCHUNK2 - 1) { CP_WAITG(1); } else { CP_WAITG(0); }
        __syncthreads();

        uint32_t Sb = sbase + (c & 1) * STAGE2;
        uint32_t AH = Sb + AH_OFF, AL = Sb + AL_OFF;
        uint32_t BH = Sb + BH_OFF, BL = Sb + BL_OFF;

#pragma unroll
        for (int ks = 0; ks < 4; ks++) {
            int kbyte = ks * 32;
            uint32_t ah[8], al[8], bh[8], bl[8];
            LDSM_X4(ah[0], ah[1], ah[2], ah[3], AH + aRowL * 128        + ((kbyte + aKofs) ^ xm));
            LDSM_X4(ah[4], ah[5], ah[6], ah[7], AH + (aRowL + 16) * 128 + ((kbyte + aKofs) ^ xm));
            LDSM_X4(bh[0], bh[1], bh[2], bh[3], BH + bRowL * 128        + ((kbyte + bKofs) ^ xm));
            LDSM_X4(bh[4], bh[5], bh[6], bh[7], BH + (bRowL + 16) * 128 + ((kbyte + bKofs) ^ xm));
            LDSM_X4(bl[0], bl[1], bl[2], bl[3], BL + bRowL * 128        + ((kbyte + bKofs) ^ xm));
            LDSM_X4(bl[4], bl[5], bl[6], bl[7], BL + (bRowL + 16) * 128 + ((kbyte + bKofs) ^ xm));
#pragma unroll
            for (int mi = 0; mi < 2; mi++)
#pragma unroll
                for (int ni = 0; ni < 4; ni++) {
                    MMA16816(acc[mi][ni], ah[mi * 4 + 0], ah[mi * 4 + 1], ah[mi * 4 + 2], ah[mi * 4 + 3],
                             bh[ni * 2 + 0], bh[ni * 2 + 1]);
                    MMA16816(acc[mi][ni], ah[mi * 4 + 0], ah[mi * 4 + 1], ah[mi * 4 + 2], ah[mi * 4 + 3],
                             bl[ni * 2 + 0], bl[ni * 2 + 1]);
                }
            LDSM_X4(al[0], al[1], al[2], al[3], AL + aRowL * 128        + ((kbyte + aKofs) ^ xm));
            LDSM_X4(al[4], al[5], al[6], al[7], AL + (aRowL + 16) * 128 + ((kbyte + aKofs) ^ xm));
#pragma unroll
            for (int mi = 0; mi < 2; mi++)
#pragma unroll
                for (int ni = 0; ni < 4; ni++)
                    MMA16816(acc[mi][ni], al[mi * 4 + 0], al[mi * 4 + 1], al[mi * 4 + 2], al[mi * 4 + 3],
                             bh[ni * 2 + 0], bh[ni * 2 + 1]);
        }
        __syncthreads();
        if (c < NCHUNK2 - 2)
            k2_issue(sbase + (c & 1) * STAGE2, m0, n0, (c + 2) * KC2, gm);
    }

    const int g = lane >> 2, t = lane & 3;
#pragma unroll
    for (int mi = 0; mi < 2; mi++) {
#pragma unroll
        for (int ni = 0; ni < 4; ni++) {
            int mg = m0 + warpM + mi * 16 + g;
            int nc = n0 + warpN + ni * 8 + 2 * t;
            float2 bvv = *(const float2*)&b3[nc];
            float2 s0 = {acc[mi][ni][0] + bvv.x, acc[mi][ni][1] + bvv.y};
            float2 s1 = {acc[mi][ni][2] + bvv.x, acc[mi][ni][3] + bvv.y};
            *(float2*)&g_W3O[(size_t)mg * NOUT + nc] = s0;
            *(float2*)&g_W3O[(size_t)(mg + 8) * NOUT + nc] = s1;
        }
    }
}

// ---------------- K3: channel-lane softmax + gather (1 warp = 1 pixel) ----------------
__global__ __launch_bounds__(256) void k3(const int* __restrict__ mY,
                                          const int* __restrict__ mX,
                                          float* __restrict__ out) {
    __shared__ float so[128 * 33];
    const int tid = threadIdx.x;
    const int wid = tid >> 5, lane = tid & 31;
    const int px0 = blockIdx.x * 32;

#pragma unroll 1
    for (int pi = 0; pi < 4; pi++) {
        int pxl = wid * 4 + pi;
        int px = px0 + pxl;
        int Y = mY[px], X = mX[px];

        const float* wr = g_W3O + (size_t)px * NOUT + lane * 18;
        float w[18];
#pragma unroll
        for (int j = 0; j < 9; j++) {
            float2 v = *(const float2*)(wr + 2 * j);
            w[2 * j] = v.x; w[2 * j + 1] = v.y;
        }
        float sw0[9], sw1[9];
        float m0v = w[0], m1v = w[9];
#pragma unroll
        for (int j = 1; j < 9; j++) { m0v = fmaxf(m0v, w[j]); m1v = fmaxf(m1v, w[9 + j]); }
        float s0 = 0.f, s1 = 0.f;
#pragma unroll
        for (int j = 0; j < 9; j++) {
            sw0[j] = __expf(w[j] - m0v);     s0 += sw0[j];
            sw1[j] = __expf(w[9 + j] - m1v); s1 += sw1[j];
        }
        float inv0 = 1.f / s0, inv1 = 1.f / s1;

        float a0x = 0.f, a0y = 0.f, a1x = 0.f, a1y = 0.f;
#pragma unroll
        for (int j = 0; j < 9; j++) {
            int yy = Y + j / 3 - 1;
            int xx = X + j % 3 - 1;
            if ((unsigned)yy < HI && (unsigned)xx < WI) {
                const float* base0 = g_XT + (size_t)((0 * HI + yy) * WI + xx) * CCH + 2 * lane;
                const float* base1 = g_XT + (size_t)((1 * HI + yy) * WI + xx) * CCH + 2 * lane;
                float2 gv0 = *(const float2*)base0;
                float2 gv1 = *(const float2*)base1;
                a0x += sw0[j] * gv0.x; a0y += sw1[j] * gv0.y;
                a1x += sw0[j] * gv1.x; a1y += sw1[j] * gv1.y;
            }
        }
        so[(0 * 64 + 2 * lane    ) * 33 + pxl] = a0x * inv0;
        so[(0 * 64 + 2 * lane + 1) * 33 + pxl] = a0y * inv1;
        so[(1 * 64 + 2 * lane    ) * 33 + pxl] = a1x * inv0;
        so[(1 * 64 + 2 * lane + 1) * 33 + pxl] = a1y * inv1;
    }
    __syncthreads();

    int row = tid >> 1, half = (tid & 1) * 16;
    float* orow = out + (size_t)row * NPIX + px0 + half;
    const float* srow = so + row * 33 + half;
#pragma unroll
    for (int i = 0; i < 4; i++) {
        float4 v = {srow[4 * i], srow[4 * i + 1], srow[4 * i + 2], srow[4 * i + 3]};
        *(float4*)&orow[4 * i] = v;
    }
}

// ---------------- launch ----------------
extern "C" void kernel_launch(void* const* d_in, const int* in_sizes, int n_in,
                              void* d_out, int out_size) {
    const float* x    = (const float*)d_in[0];
    const float* pose = (const float*)d_in[1];
    const float* W1   = (const float*)d_in[2];
    const float* b1   = (const float*)d_in[3];
    const float* W2   = (const float*)d_in[4];
    const float* b2   = (const float*)d_in[5];
    const float* W3   = (const float*)d_in[6];
    const float* b3   = (const float*)d_in[7];
    const int*   mY   = (const int*)d_in[8];
    const int*   mX   = (const int*)d_in[9];
    float* out = (float*)d_out;

    cudaFuncSetAttribute(k2, cudaFuncAttributeMaxDynamicSharedMemorySize, K2_SMEM);
    cudaFuncSetAttribute(k1, cudaFuncAttributeMaxDynamicSharedMemorySize, K1_SMEM);

    prep_w<<<(NOUT * 256 + 255) / 256, 256>>>(W2, W3);
    prep_x<<<(2 * HI * WI * CCH + 255) / 256, 256>>>(x);
    k1<<<NPIX / 128, 512, K1_SMEM>>>(pose, W1, b1, b2);
    dim3 g2(NOUT / 64, NPIX / 128);
    k2<<<g2, 256, K2_SMEM>>>(b3);
    k3<<<NPIX / 32, 256>>>(mY, mX, out);
}

// round 7
// speedup vs baseline: 3.7900x; 1.0720x over previous
#include <cuda_runtime.h>
#include <cuda_bf16.h>
#include <cstdint>

#define NPIX   262144      // 512*512
#define HI     128
#define WI     128
#define CCH    64
#define NOUT   576         // C*KS*KS

// ---------------- scratch (device globals; no allocation) ----------------
__device__ __nv_bfloat16 g_H2h[(size_t)NPIX * 256];  // bf16 hi of relu(layer2), [pix][256]
__device__ __nv_bfloat16 g_H2l[(size_t)NPIX * 256];  // bf16 lo residual
__device__ __nv_bfloat16 g_W3h[NOUT * 256];          // bf16 hi of W3, native [n][k]
__device__ __nv_bfloat16 g_W3l[NOUT * 256];          // bf16 lo residual
__device__ __nv_bfloat16 g_W2h[256 * 64];            // bf16 hi of W2, native [n][k]
__device__ __nv_bfloat16 g_W2l[256 * 64];            // bf16 lo residual
__device__ float g_W3O[(size_t)NPIX * NOUT];         // layer-3 logits, [pix][576]
__device__ float g_XT [2 * HI * WI * CCH];           // x transposed to [b][y][x][c]

__device__ __forceinline__ uint32_t smem_u32(const void* p) {
    uint32_t a;
    asm("{ .reg .u64 t; cvta.to.shared.u64 t, %1; cvt.u32.u64 %0, t; }" : "=r"(a) : "l"(p));
    return a;
}

#define CP16(dst, src) \
    asm volatile("cp.async.cg.shared.global [%0], [%1], 16;" :: "r"(dst), "l"(src))
#define CP_COMMIT() asm volatile("cp.async.commit_group;")
#define CP_WAITG(n) asm volatile("cp.async.wait_group %0;" :: "n"(n))

#define LDSM_X4(r0, r1, r2, r3, a) \
    asm volatile("ldmatrix.sync.aligned.m8n8.x4.shared.b16 {%0,%1,%2,%3}, [%4];" \
        : "=r"(r0), "=r"(r1), "=r"(r2), "=r"(r3) : "r"(a))

#define MMA16816(d, a0, a1, a2, a3, b0, b1) \
    asm volatile("mma.sync.aligned.m16n8k16.row.col.f32.bf16.bf16.f32 " \
        "{%0,%1,%2,%3}, {%4,%5,%6,%7}, {%8,%9}, {%0,%1,%2,%3};" \
        : "+f"((d)[0]), "+f"((d)[1]), "+f"((d)[2]), "+f"((d)[3]) \
        : "r"(a0), "r"(a1), "r"(a2), "r"(a3), "r"(b0), "r"(b1))

// ---------------- prep: weight bf16 splits ----------------
__global__ void prep_w(const float* __restrict__ W2, const float* __restrict__ W3) {
    int idx = blockIdx.x * blockDim.x + threadIdx.x;
    if (idx < 256 * 64) {            // W2 native [n][k]
        float v = W2[idx];
        __nv_bfloat16 h = __float2bfloat16(v);
        g_W2h[idx] = h;
        g_W2l[idx] = __float2bfloat16(v - __bfloat162float(h));
    }
    if (idx < NOUT * 256) {          // W3 native [n][k]
        float v = W3[idx];
        __nv_bfloat16 h = __float2bfloat16(v);
        g_W3h[idx] = h;
        g_W3l[idx] = __float2bfloat16(v - __bfloat162float(h));
    }
}

// ---------------- prep: x NCHW -> NHWC ----------------
__global__ void prep_x(const float* __restrict__ x) {
    int o = blockIdx.x * blockDim.x + threadIdx.x;
    if (o >= 2 * HI * WI * CCH) return;
    int c = o & 63;
    int t = o >> 6;
    int xx = t & (WI - 1); t >>= 7;
    int y  = t & (HI - 1); t >>= 7;
    int b  = t;
    g_XT[o] = x[(((b * CCH + c) * HI + y) * WI) + xx];
}

// ---------------- K1: HMMA layer-2 GEMM with inline h1 producer ----------------
// H2[262144 x 256] = relu( h1[262144 x 64] * W2^T + b2 ), h1 computed in-loader.
// M=128 px, N=64 ch, K=64 single stage. 3-term bf16 split.
#define K1_AH 0
#define K1_AL 16384
#define K1_BH 32768
#define K1_BL 40960
#define K1_SMEM 49152

__global__ __launch_bounds__(256) void k1(const float* __restrict__ pose,
                                          const float* __restrict__ W1,
                                          const float* __restrict__ b1,
                                          const float* __restrict__ b2) {
    extern __shared__ __align__(128) char sm[];
    const uint32_t sbase = smem_u32(sm);
    __shared__ float w1s[192];
    __shared__ float b1s[64];

    const int tid = threadIdx.x;
    const int wid = tid >> 5, lane = tid & 31;
    const int n0 = blockIdx.x * 64;
    const int m0 = blockIdx.y * 128;

    if (tid < 192) w1s[tid] = W1[tid];
    if (tid < 64)  b1s[tid] = b1[tid];

    // ---- B loader: W2h/W2l rows [n0..n0+64) x 64k (128B rows, swizzled) ----
#pragma unroll
    for (int i = 0; i < 2; i++) {
        int o = tid + i * 256;
        int row = o >> 3, g = o & 7;
        uint32_t dst = row * 128 + ((g * 16) ^ ((row & 7) << 4));
        size_t src = (size_t)(n0 + row) * 64 + g * 8;
        CP16(sbase + K1_BH + dst, g_W2h + src);
        CP16(sbase + K1_BL + dst, g_W2l + src);
    }
    CP_COMMIT();
    __syncthreads();   // w1s/b1s ready

    // ---- A producer: h1 = relu(W1*pose + b1), split to bf16, swizzled store ----
    {
        int row = tid >> 1;              // pixel row 0..127
        int ch0 = (tid & 1) * 32;        // channel half
        int px = m0 + row;
        float p0 = pose[px], p1 = pose[NPIX + px], p2 = pose[2 * NPIX + px];
#pragma unroll
        for (int g = 0; g < 4; g++) {
            __nv_bfloat16 hi8[8], lo8[8];
#pragma unroll
            for (int j = 0; j < 8; j++) {
                int c = ch0 + g * 8 + j;
                float v = fmaf(w1s[c * 3], p0,
                          fmaf(w1s[c * 3 + 1], p1,
                          fmaf(w1s[c * 3 + 2], p2, b1s[c])));
                v = fmaxf(v, 0.f);
                __nv_bfloat16 h = __float2bfloat16(v);
                hi8[j] = h;
                lo8[j] = __float2bfloat16(v - __bfloat162float(h));
            }
            int grp = ch0 / 8 + g;
            uint32_t dst = row * 128 + ((grp * 16) ^ ((row & 7) << 4));
            *(uint4*)(sm + K1_AH + dst) = *(const uint4*)hi8;
            *(uint4*)(sm + K1_AL + dst) = *(const uint4*)lo8;
        }
    }
    CP_WAITG(0);
    __syncthreads();

    // ---- MMA: warp tile 32x32, 4 k-steps, 3 terms ----
    const int warpM = (wid >> 1) * 32;
    const int warpN = (wid & 1) * 32;
    const int q = lane >> 3, r8 = lane & 7;
    const int xm = r8 << 4;
    const int aRowL = warpM + ((q & 1) << 3) + r8;
    const int aKofs = (q >> 1) << 4;
    const int bRowL = warpN + ((q >> 1) << 3) + r8;
    const int bKofs = (q & 1) << 4;

    const uint32_t AH = sbase + K1_AH, AL = sbase + K1_AL;
    const uint32_t BH = sbase + K1_BH, BL = sbase + K1_BL;

    float acc[2][4][4] = {};
#pragma unroll
    for (int ks = 0; ks < 4; ks++) {
        int kbyte = ks * 32;
        uint32_t ah[8], al[8], bh[8], bl[8];
        LDSM_X4(ah[0], ah[1], ah[2], ah[3], AH + aRowL * 128        + ((kbyte + aKofs) ^ xm));
        LDSM_X4(ah[4], ah[5], ah[6], ah[7], AH + (aRowL + 16) * 128 + ((kbyte + aKofs) ^ xm));
        LDSM_X4(bh[0], bh[1], bh[2], bh[3], BH + bRowL * 128        + ((kbyte + bKofs) ^ xm));
        LDSM_X4(bh[4], bh[5], bh[6], bh[7], BH + (bRowL + 16) * 128 + ((kbyte + bKofs) ^ xm));
        LDSM_X4(bl[0], bl[1], bl[2], bl[3], BL + bRowL * 128        + ((kbyte + bKofs) ^ xm));
        LDSM_X4(bl[4], bl[5], bl[6], bl[7], BL + (bRowL + 16) * 128 + ((kbyte + bKofs) ^ xm));
#pragma unroll
        for (int mi = 0; mi < 2; mi++)
#pragma unroll
            for (int ni = 0; ni < 4; ni++) {
                MMA16816(acc[mi][ni], ah[mi * 4 + 0], ah[mi * 4 + 1], ah[mi * 4 + 2], ah[mi * 4 + 3],
                         bh[ni * 2 + 0], bh[ni * 2 + 1]);
                MMA16816(acc[mi][ni], ah[mi * 4 + 0], ah[mi * 4 + 1], ah[mi * 4 + 2], ah[mi * 4 + 3],
                         bl[ni * 2 + 0], bl[ni * 2 + 1]);
            }
        LDSM_X4(al[0], al[1], al[2], al[3], AL + aRowL * 128        + ((kbyte + aKofs) ^ xm));
        LDSM_X4(al[4], al[5], al[6], al[7], AL + (aRowL + 16) * 128 + ((kbyte + aKofs) ^ xm));
#pragma unroll
        for (int mi = 0; mi < 2; mi++)
#pragma unroll
            for (int ni = 0; ni < 4; ni++)
                MMA16816(acc[mi][ni], al[mi * 4 + 0], al[mi * 4 + 1], al[mi * 4 + 2], al[mi * 4 + 3],
                         bh[ni * 2 + 0], bh[ni * 2 + 1]);
    }

    // ---- epilogue: +b2, relu, bf16 split, store H2h/H2l ----
    const int g = lane >> 2, t = lane & 3;
#pragma unroll
    for (int mi = 0; mi < 2; mi++) {
#pragma unroll
        for (int ni = 0; ni < 4; ni++) {
            int nc = n0 + warpN + ni * 8 + 2 * t;
            float bv0 = b2[nc], bv1 = b2[nc + 1];
#pragma unroll
            for (int r = 0; r < 2; r++) {
                int px = m0 + warpM + mi * 16 + g + r * 8;
                float v0 = fmaxf(acc[mi][ni][2 * r + 0] + bv0, 0.f);
                float v1 = fmaxf(acc[mi][ni][2 * r + 1] + bv1, 0.f);
                __nv_bfloat16 h0 = __float2bfloat16(v0);
                __nv_bfloat16 h1v = __float2bfloat16(v1);
                __nv_bfloat16 l0 = __float2bfloat16(v0 - __bfloat162float(h0));
                __nv_bfloat16 l1 = __float2bfloat16(v1 - __bfloat162float(h1v));
                __nv_bfloat162 hp; hp.x = h0; hp.y = h1v;
                __nv_bfloat162 lp; lp.x = l0; lp.y = l1;
                size_t base = (size_t)px * 256 + nc;
                *(__nv_bfloat162*)&g_H2h[base] = hp;
                *(__nv_bfloat162*)&g_H2l[base] = lp;
            }
        }
    }
}

// ---------------- K2: combined-chunk bf16-split HMMA GEMM (unchanged) ----------------
#define KC2      64
#define NCHUNK2  4
#define AH_OFF   0
#define AL_OFF   16384
#define BH_OFF   32768
#define BL_OFF   40960
#define STAGE2   49152
#define K2_SMEM  (2 * STAGE2)     // 98304

struct K2Geom {
    int aRow[4], aDst[4], bRow[2], bDst[2], grp8;
};

__device__ __forceinline__ void k2_issue(uint32_t sb, int m0, int n0, int kb, const K2Geom& g) {
#pragma unroll
    for (int i = 0; i < 4; i++) {
        size_t asrc = (size_t)(m0 + g.aRow[i]) * 256 + kb + g.grp8;
        CP16(sb + AH_OFF + g.aDst[i], g_H2h + asrc);
        CP16(sb + AL_OFF + g.aDst[i], g_H2l + asrc);
    }
#pragma unroll
    for (int i = 0; i < 2; i++) {
        size_t bsrc = (size_t)(n0 + g.bRow[i]) * 256 + kb + g.grp8;
        CP16(sb + BH_OFF + g.bDst[i], g_W3h + bsrc);
        CP16(sb + BL_OFF + g.bDst[i], g_W3l + bsrc);
    }
    CP_COMMIT();
}

__global__ __launch_bounds__(256) void k2(const float* __restrict__ b3) {
    extern __shared__ __align__(128) char smem[];
    const uint32_t sbase = smem_u32(smem);
    const int tid = threadIdx.x;
    const int wid = tid >> 5, lane = tid & 31;

    const int n0 = blockIdx.x * 64;
    const int m0 = blockIdx.y * 128;

    K2Geom gm;
    gm.grp8 = (tid & 7) * 8;
#pragma unroll
    for (int i = 0; i < 4; i++) {
        int o = tid + i * 256;
        int row = o >> 3, grp = o & 7;
        gm.aRow[i] = row;
        gm.aDst[i] = row * 128 + ((grp * 16) ^ ((row & 7) << 4));
    }
#pragma unroll
    for (int i = 0; i < 2; i++) {
        int o = tid + i * 256;
        int row = o >> 3, grp = o & 7;
        gm.bRow[i] = row;
        gm.bDst[i] = row * 128 + ((grp * 16) ^ ((row & 7) << 4));
    }

    k2_issue(sbase + 0 * STAGE2, m0, n0, 0 * KC2, gm);
    k2_issue(sbase + 1 * STAGE2, m0, n0, 1 * KC2, gm);

    const int warpM = (wid >> 1) * 32;
    const int warpN = (wid & 1) * 32;
    const int q = lane >> 3, r8 = lane & 7;
    const int xm = r8 << 4;
    const int aRowL = warpM + ((q & 1) << 3) + r8;
    const int aKofs = (q >> 1) << 4;
    const int bRowL = warpN + ((q >> 1) << 3) + r8;
    const int bKofs = (q & 1) << 4;

    float acc[2][4][4] = {};

#pragma unroll 1
    for (int c = 0; c < NCHUNK2; c++) {
        if (c < NCHUNK2 - 1) { CP_WAITG(1); } else { CP_WAITG(0); }
        __syncthreads();

        uint32_t Sb = sbase + (c & 1) * STAGE2;
        uint32_t AH = Sb + AH_OFF, AL = Sb + AL_OFF;
        uint32_t BH = Sb + BH_OFF, BL = Sb + BL_OFF;

#pragma unroll
        for (int ks = 0; ks < 4; ks++) {
            int kbyte = ks * 32;
            uint32_t ah[8], al[8], bh[8], bl[8];
            LDSM_X4(ah[0], ah[1], ah[2], ah[3], AH + aRowL * 128        + ((kbyte + aKofs) ^ xm));
            LDSM_X4(ah[4], ah[5], ah[6], ah[7], AH + (aRowL + 16) * 128 + ((kbyte + aKofs) ^ xm));
            LDSM_X4(bh[0], bh[1], bh[2], bh[3], BH + bRowL * 128        + ((kbyte + bKofs) ^ xm));
            LDSM_X4(bh[4], bh[5], bh[6], bh[7], BH + (bRowL + 16) * 128 + ((kbyte + bKofs) ^ xm));
            LDSM_X4(bl[0], bl[1], bl[2], bl[3], BL + bRowL * 128        + ((kbyte + bKofs) ^ xm));
            LDSM_X4(bl[4], bl[5], bl[6], bl[7], BL + (bRowL + 16) * 128 + ((kbyte + bKofs) ^ xm));
#pragma unroll
            for (int mi = 0; mi < 2; mi++)
#pragma unroll
                for (int ni = 0; ni < 4; ni++) {
                    MMA16816(acc[mi][ni], ah[mi * 4 + 0], ah[mi * 4 + 1], ah[mi * 4 + 2], ah[mi * 4 + 3],
                             bh[ni * 2 + 0], bh[ni * 2 + 1]);
                    MMA16816(acc[mi][ni], ah[mi * 4 + 0], ah[mi * 4 + 1], ah[mi * 4 + 2], ah[mi * 4 + 3],
                             bl[ni * 2 + 0], bl[ni * 2 + 1]);
                }
            LDSM_X4(al[0], al[1], al[2], al[3], AL + aRowL * 128        + ((kbyte + aKofs) ^ xm));
            LDSM_X4(al[4], al[5], al[6], al[7], AL + (aRowL + 16) * 128 + ((kbyte + aKofs) ^ xm));
#pragma unroll
            for (int mi = 0; mi < 2; mi++)
#pragma unroll
                for (int ni = 0; ni < 4; ni++)
                    MMA16816(acc[mi][ni], al[mi * 4 + 0], al[mi * 4 + 1], al[mi * 4 + 2], al[mi * 4 + 3],
                             bh[ni * 2 + 0], bh[ni * 2 + 1]);
        }
        __syncthreads();
        if (c < NCHUNK2 - 2)
            k2_issue(sbase + (c & 1) * STAGE2, m0, n0, (c + 2) * KC2, gm);
    }

    const int g = lane >> 2, t = lane & 3;
#pragma unroll
    for (int mi = 0; mi < 2; mi++) {
#pragma unroll
        for (int ni = 0; ni < 4; ni++) {
            int mg = m0 + warpM + mi * 16 + g;
            int nc = n0 + warpN + ni * 8 + 2 * t;
            float2 bvv = *(const float2*)&b3[nc];
            float2 s0 = {acc[mi][ni][0] + bvv.x, acc[mi][ni][1] + bvv.y};
            float2 s1 = {acc[mi][ni][2] + bvv.x, acc[mi][ni][3] + bvv.y};
            *(float2*)&g_W3O[(size_t)mg * NOUT + nc] = s0;
            *(float2*)&g_W3O[(size_t)(mg + 8) * NOUT + nc] = s1;
        }
    }
}

// ---------------- K3: channel-lane softmax + gather (1 warp = 1 pixel) ----------------
__global__ __launch_bounds__(256) void k3(const int* __restrict__ mY,
                                          const int* __restrict__ mX,
                                          float* __restrict__ out) {
    __shared__ float so[128 * 33];
    const int tid = threadIdx.x;
    const int wid = tid >> 5, lane = tid & 31;
    const int px0 = blockIdx.x * 32;

#pragma unroll 1
    for (int pi = 0; pi < 4; pi++) {
        int pxl = wid * 4 + pi;
        int px = px0 + pxl;
        int Y = mY[px], X = mX[px];

        const float* wr = g_W3O + (size_t)px * NOUT + lane * 18;
        float w[18];
#pragma unroll
        for (int j = 0; j < 9; j++) {
            float2 v = *(const float2*)(wr + 2 * j);
            w[2 * j] = v.x; w[2 * j + 1] = v.y;
        }
        float sw0[9], sw1[9];
        float m0v = w[0], m1v = w[9];
#pragma unroll
        for (int j = 1; j < 9; j++) { m0v = fmaxf(m0v, w[j]); m1v = fmaxf(m1v, w[9 + j]); }
        float s0 = 0.f, s1 = 0.f;
#pragma unroll
        for (int j = 0; j < 9; j++) {
            sw0[j] = __expf(w[j] - m0v);     s0 += sw0[j];
            sw1[j] = __expf(w[9 + j] - m1v); s1 += sw1[j];
        }
        float inv0 = 1.f / s0, inv1 = 1.f / s1;

        float a0x = 0.f, a0y = 0.f, a1x = 0.f, a1y = 0.f;
#pragma unroll
        for (int j = 0; j < 9; j++) {
            int yy = Y + j / 3 - 1;
            int xx = X + j % 3 - 1;
            if ((unsigned)yy < HI && (unsigned)xx < WI) {
                const float* base0 = g_XT + (size_t)((0 * HI + yy) * WI + xx) * CCH + 2 * lane;
                const float* base1 = g_XT + (size_t)((1 * HI + yy) * WI + xx) * CCH + 2 * lane;
                float2 gv0 = *(const float2*)base0;
                float2 gv1 = *(const float2*)base1;
                a0x += sw0[j] * gv0.x; a0y += sw1[j] * gv0.y;
                a1x += sw0[j] * gv1.x; a1y += sw1[j] * gv1.y;
            }
        }
        so[(0 * 64 + 2 * lane    ) * 33 + pxl] = a0x * inv0;
        so[(0 * 64 + 2 * lane + 1) * 33 + pxl] = a0y * inv1;
        so[(1 * 64 + 2 * lane    ) * 33 + pxl] = a1x * inv0;
        so[(1 * 64 + 2 * lane + 1) * 33 + pxl] = a1y * inv1;
    }
    __syncthreads();

    int row = tid >> 1, half = (tid & 1) * 16;
    float* orow = out + (size_t)row * NPIX + px0 + half;
    const float* srow = so + row * 33 + half;
#pragma unroll
    for (int i = 0; i < 4; i++) {
        float4 v = {srow[4 * i], srow[4 * i + 1], srow[4 * i + 2], srow[4 * i + 3]};
        *(float4*)&orow[4 * i] = v;
    }
}

// ---------------- launch ----------------
extern "C" void kernel_launch(void* const* d_in, const int* in_sizes, int n_in,
                              void* d_out, int out_size) {
    const float* x    = (const float*)d_in[0];
    const float* pose = (const float*)d_in[1];
    const float* W1   = (const float*)d_in[2];
    const float* b1   = (const float*)d_in[3];
    const float* W2   = (const float*)d_in[4];
    const float* b2   = (const float*)d_in[5];
    const float* W3   = (const float*)d_in[6];
    const float* b3   = (const float*)d_in[7];
    const int*   mY   = (const int*)d_in[8];
    const int*   mX   = (const int*)d_in[9];
    float* out = (float*)d_out;

    cudaFuncSetAttribute(k2, cudaFuncAttributeMaxDynamicSharedMemorySize, K2_SMEM);
    cudaFuncSetAttribute(k1, cudaFuncAttributeMaxDynamicSharedMemorySize, K1_SMEM);

    prep_w<<<(NOUT * 256 + 255) / 256, 256>>>(W2, W3);
    prep_x<<<(2 * HI * WI * CCH + 255) / 256, 256>>>(x);
    dim3 g1(256 / 64, NPIX / 128);
    k1<<<g1, 256, K1_SMEM>>>(pose, W1, b1, b2);
    dim3 g2(NOUT / 64, NPIX / 128);
    k2<<<g2, 256, K2_SMEM>>>(b3);
    k3<<<NPIX / 32, 256>>>(mY, mX, out);
}

// round 8
// speedup vs baseline: 3.9406x; 1.0398x over previous
#include <cuda_runtime.h>
#include <cuda_bf16.h>
#include <cstdint>

#define NPIX   262144      // 512*512
#define HI     128
#define WI     128
#define CCH    64
#define NOUT   576         // C*KS*KS

// ---------------- scratch (device globals; no allocation) ----------------
__device__ __nv_bfloat16 g_H2h[(size_t)NPIX * 256];  // bf16 hi of relu(layer2), [pix][256]
__device__ __nv_bfloat16 g_H2l[(size_t)NPIX * 256];  // bf16 lo residual
__device__ __nv_bfloat16 g_W3h[NOUT * 256];          // bf16 hi of W3, native [n][k]
__device__ __nv_bfloat16 g_W3l[NOUT * 256];          // bf16 lo residual
__device__ __nv_bfloat16 g_W2h[256 * 64];            // bf16 hi of W2, native [n][k]
__device__ __nv_bfloat16 g_W2l[256 * 64];            // bf16 lo residual
__device__ float g_W3O[(size_t)NPIX * NOUT];         // layer-3 logits, [pix][576]
__device__ float g_XT [2 * HI * WI * CCH];           // x transposed to [b][y][x][c]

__device__ __forceinline__ uint32_t smem_u32(const void* p) {
    uint32_t a;
    asm("{ .reg .u64 t; cvta.to.shared.u64 t, %1; cvt.u32.u64 %0, t; }" : "=r"(a) : "l"(p));
    return a;
}

#define CP16(dst, src) \
    asm volatile("cp.async.cg.shared.global [%0], [%1], 16;" :: "r"(dst), "l"(src))
#define CP_COMMIT() asm volatile("cp.async.commit_group;")
#define CP_WAITG(n) asm volatile("cp.async.wait_group %0;" :: "n"(n))

#define LDSM_X4(r0, r1, r2, r3, a) \
    asm volatile("ldmatrix.sync.aligned.m8n8.x4.shared.b16 {%0,%1,%2,%3}, [%4];" \
        : "=r"(r0), "=r"(r1), "=r"(r2), "=r"(r3) : "r"(a))

#define MMA16816(d, a0, a1, a2, a3, b0, b1) \
    asm volatile("mma.sync.aligned.m16n8k16.row.col.f32.bf16.bf16.f32 " \
        "{%0,%1,%2,%3}, {%4,%5,%6,%7}, {%8,%9}, {%0,%1,%2,%3};" \
        : "+f"((d)[0]), "+f"((d)[1]), "+f"((d)[2]), "+f"((d)[3]) \
        : "r"(a0), "r"(a1), "r"(a2), "r"(a3), "r"(b0), "r"(b1))

// ---------------- prep: weight bf16 splits ----------------
__global__ void prep_w(const float* __restrict__ W2, const float* __restrict__ W3) {
    int idx = blockIdx.x * blockDim.x + threadIdx.x;
    if (idx < 256 * 64) {
        float v = W2[idx];
        __nv_bfloat16 h = __float2bfloat16(v);
        g_W2h[idx] = h;
        g_W2l[idx] = __float2bfloat16(v - __bfloat162float(h));
    }
    if (idx < NOUT * 256) {
        float v = W3[idx];
        __nv_bfloat16 h = __float2bfloat16(v);
        g_W3h[idx] = h;
        g_W3l[idx] = __float2bfloat16(v - __bfloat162float(h));
    }
}

// ---------------- prep: x NCHW -> NHWC ----------------
__global__ void prep_x(const float* __restrict__ x) {
    int o = blockIdx.x * blockDim.x + threadIdx.x;
    if (o >= 2 * HI * WI * CCH) return;
    int c = o & 63;
    int t = o >> 6;
    int xx = t & (WI - 1); t >>= 7;
    int y  = t & (HI - 1); t >>= 7;
    int b  = t;
    g_XT[o] = x[(((b * CCH + c) * HI + y) * WI) + xx];
}

// ---------------- K1: HMMA layer-2 GEMM with inline h1 producer ----------------
#define K1_AH 0
#define K1_AL 16384
#define K1_BH 32768
#define K1_BL 40960
#define K1_SMEM 49152

__global__ __launch_bounds__(256) void k1(const float* __restrict__ pose,
                                          const float* __restrict__ W1,
                                          const float* __restrict__ b1,
                                          const float* __restrict__ b2) {
    extern __shared__ __align__(128) char sm[];
    const uint32_t sbase = smem_u32(sm);
    __shared__ float w1s[192];
    __shared__ float b1s[64];

    const int tid = threadIdx.x;
    const int wid = tid >> 5, lane = tid & 31;
    const int n0 = blockIdx.x * 64;
    const int m0 = blockIdx.y * 128;

    if (tid < 192) w1s[tid] = W1[tid];
    if (tid < 64)  b1s[tid] = b1[tid];

#pragma unroll
    for (int i = 0; i < 2; i++) {
        int o = tid + i * 256;
        int row = o >> 3, g = o & 7;
        uint32_t dst = row * 128 + ((g * 16) ^ ((row & 7) << 4));
        size_t src = (size_t)(n0 + row) * 64 + g * 8;
        CP16(sbase + K1_BH + dst, g_W2h + src);
        CP16(sbase + K1_BL + dst, g_W2l + src);
    }
    CP_COMMIT();
    __syncthreads();

    {
        int row = tid >> 1;
        int ch0 = (tid & 1) * 32;
        int px = m0 + row;
        float p0 = pose[px], p1 = pose[NPIX + px], p2 = pose[2 * NPIX + px];
#pragma unroll
        for (int g = 0; g < 4; g++) {
            __nv_bfloat16 hi8[8], lo8[8];
#pragma unroll
            for (int j = 0; j < 8; j++) {
                int c = ch0 + g * 8 + j;
                float v = fmaf(w1s[c * 3], p0,
                          fmaf(w1s[c * 3 + 1], p1,
                          fmaf(w1s[c * 3 + 2], p2, b1s[c])));
                v = fmaxf(v, 0.f);
                __nv_bfloat16 h = __float2bfloat16(v);
                hi8[j] = h;
                lo8[j] = __float2bfloat16(v - __bfloat162float(h));
            }
            int grp = ch0 / 8 + g;
            uint32_t dst = row * 128 + ((grp * 16) ^ ((row & 7) << 4));
            *(uint4*)(sm + K1_AH + dst) = *(const uint4*)hi8;
            *(uint4*)(sm + K1_AL + dst) = *(const uint4*)lo8;
        }
    }
    CP_WAITG(0);
    __syncthreads();

    const int warpM = (wid >> 1) * 32;
    const int warpN = (wid & 1) * 32;
    const int q = lane >> 3, r8 = lane & 7;
    const int xm = r8 << 4;
    const int aRowL = warpM + ((q & 1) << 3) + r8;
    const int aKofs = (q >> 1) << 4;
    const int bRowL = warpN + ((q >> 1) << 3) + r8;
    const int bKofs = (q & 1) << 4;

    const uint32_t AH = sbase + K1_AH, AL = sbase + K1_AL;
    const uint32_t BH = sbase + K1_BH, BL = sbase + K1_BL;

    float acc[2][4][4] = {};
#pragma unroll
    for (int ks = 0; ks < 4; ks++) {
        int kbyte = ks * 32;
        uint32_t ah[8], al[8], bh[8], bl[8];
        LDSM_X4(ah[0], ah[1], ah[2], ah[3], AH + aRowL * 128        + ((kbyte + aKofs) ^ xm));
        LDSM_X4(ah[4], ah[5], ah[6], ah[7], AH + (aRowL + 16) * 128 + ((kbyte + aKofs) ^ xm));
        LDSM_X4(al[0], al[1], al[2], al[3], AL + aRowL * 128        + ((kbyte + aKofs) ^ xm));
        LDSM_X4(al[4], al[5], al[6], al[7], AL + (aRowL + 16) * 128 + ((kbyte + aKofs) ^ xm));
        LDSM_X4(bh[0], bh[1], bh[2], bh[3], BH + bRowL * 128        + ((kbyte + bKofs) ^ xm));
        LDSM_X4(bh[4], bh[5], bh[6], bh[7], BH + (bRowL + 16) * 128 + ((kbyte + bKofs) ^ xm));
        LDSM_X4(bl[0], bl[1], bl[2], bl[3], BL + bRowL * 128        + ((kbyte + bKofs) ^ xm));
        LDSM_X4(bl[4], bl[5], bl[6], bl[7], BL + (bRowL + 16) * 128 + ((kbyte + bKofs) ^ xm));
#pragma unroll
        for (int mi = 0; mi < 2; mi++)
#pragma unroll
            for (int ni = 0; ni < 4; ni++) {
                MMA16816(acc[mi][ni], ah[mi * 4 + 0], ah[mi * 4 + 1], ah[mi * 4 + 2], ah[mi * 4 + 3],
                         bh[ni * 2 + 0], bh[ni * 2 + 1]);
                MMA16816(acc[mi][ni], ah[mi * 4 + 0], ah[mi * 4 + 1], ah[mi * 4 + 2], ah[mi * 4 + 3],
                         bl[ni * 2 + 0], bl[ni * 2 + 1]);
                MMA16816(acc[mi][ni], al[mi * 4 + 0], al[mi * 4 + 1], al[mi * 4 + 2], al[mi * 4 + 3],
                         bh[ni * 2 + 0], bh[ni * 2 + 1]);
            }
    }

    const int g = lane >> 2, t = lane & 3;
#pragma unroll
    for (int mi = 0; mi < 2; mi++) {
#pragma unroll
        for (int ni = 0; ni < 4; ni++) {
            int nc = n0 + warpN + ni * 8 + 2 * t;
            float bv0 = b2[nc], bv1 = b2[nc + 1];
#pragma unroll
            for (int r = 0; r < 2; r++) {
                int px = m0 + warpM + mi * 16 + g + r * 8;
                float v0 = fmaxf(acc[mi][ni][2 * r + 0] + bv0, 0.f);
                float v1 = fmaxf(acc[mi][ni][2 * r + 1] + bv1, 0.f);
                __nv_bfloat16 h0 = __float2bfloat16(v0);
                __nv_bfloat16 h1v = __float2bfloat16(v1);
                __nv_bfloat16 l0 = __float2bfloat16(v0 - __bfloat162float(h0));
                __nv_bfloat16 l1 = __float2bfloat16(v1 - __bfloat162float(h1v));
                __nv_bfloat162 hp; hp.x = h0; hp.y = h1v;
                __nv_bfloat162 lp; lp.x = l0; lp.y = l1;
                size_t base = (size_t)px * 256 + nc;
                *(__nv_bfloat162*)&g_H2h[base] = hp;
                *(__nv_bfloat162*)&g_H2l[base] = lp;
            }
        }
    }
}

// ---------------- K2: combined-chunk bf16-split HMMA GEMM ----------------
#define KC2      64
#define NCHUNK2  4
#define AH_OFF   0
#define AL_OFF   16384
#define BH_OFF   32768
#define BL_OFF   40960
#define STAGE2   49152
#define K2_SMEM  (2 * STAGE2)     // 98304

struct K2Geom {
    int aRow[4], aDst[4], bRow[2], bDst[2], grp8;
};

__device__ __forceinline__ void k2_issue(uint32_t sb, int m0, int n0, int kb, const K2Geom& g) {
#pragma unroll
    for (int i = 0; i < 4; i++) {
        size_t asrc = (size_t)(m0 + g.aRow[i]) * 256 + kb + g.grp8;
        CP16(sb + AH_OFF + g.aDst[i], g_H2h + asrc);
        CP16(sb + AL_OFF + g.aDst[i], g_H2l + asrc);
    }
#pragma unroll
    for (int i = 0; i < 2; i++) {
        size_t bsrc = (size_t)(n0 + g.bRow[i]) * 256 + kb + g.grp8;
        CP16(sb + BH_OFF + g.bDst[i], g_W3h + bsrc);
        CP16(sb + BL_OFF + g.bDst[i], g_W3l + bsrc);
    }
    CP_COMMIT();
}

__global__ __launch_bounds__(256, 2) void k2(const float* __restrict__ b3) {
    extern __shared__ __align__(128) char smem[];
    const uint32_t sbase = smem_u32(smem);
    const int tid = threadIdx.x;
    const int wid = tid >> 5, lane = tid & 31;

    const int n0 = blockIdx.x * 64;
    const int m0 = blockIdx.y * 128;

    K2Geom gm;
    gm.grp8 = (tid & 7) * 8;
#pragma unroll
    for (int i = 0; i < 4; i++) {
        int o = tid + i * 256;
        int row = o >> 3, grp = o & 7;
        gm.aRow[i] = row;
        gm.aDst[i] = row * 128 + ((grp * 16) ^ ((row & 7) << 4));
    }
#pragma unroll
    for (int i = 0; i < 2; i++) {
        int o = tid + i * 256;
        int row = o >> 3, grp = o & 7;
        gm.bRow[i] = row;
        gm.bDst[i] = row * 128 + ((grp * 16) ^ ((row & 7) << 4));
    }

    k2_issue(sbase + 0 * STAGE2, m0, n0, 0 * KC2, gm);
    k2_issue(sbase + 1 * STAGE2, m0, n0, 1 * KC2, gm);

    const int warpM = (wid >> 1) * 32;
    const int warpN = (wid & 1) * 32;
    const int q = lane >> 3, r8 = lane & 7;
    const int xm = r8 << 4;
    const int aRowL = warpM + ((q & 1) << 3) + r8;
    const int aKofs = (q >> 1) << 4;
    const int bRowL = warpN + ((q >> 1) << 3) + r8;
    const int bKofs = (q & 1) << 4;

    float acc[2][4][4] = {};

#pragma unroll 1
    for (int c = 0; c < NCHUNK2; c++) {
        if (c < NCHUNK2 - 1) { CP_WAITG(1); } else { CP_WAITG(0); }
        __syncthreads();

        uint32_t Sb = sbase + (c & 1) * STAGE2;
        uint32_t AH = Sb + AH_OFF, AL = Sb + AL_OFF;
        uint32_t BH = Sb + BH_OFF, BL = Sb + BL_OFF;

#pragma unroll
        for (int ks = 0; ks < 4; ks++) {
            int kbyte = ks * 32;
            uint32_t ah[8], al[8], bh[8], bl[8];
            LDSM_X4(ah[0], ah[1], ah[2], ah[3], AH + aRowL * 128        + ((kbyte + aKofs) ^ xm));
            LDSM_X4(ah[4], ah[5], ah[6], ah[7], AH + (aRowL + 16) * 128 + ((kbyte + aKofs) ^ xm));
            LDSM_X4(al[0], al[1], al[2], al[3], AL + aRowL * 128        + ((kbyte + aKofs) ^ xm));
            LDSM_X4(al[4], al[5], al[6], al[7], AL + (aRowL + 16) * 128 + ((kbyte + aKofs) ^ xm));
            LDSM_X4(bh[0], bh[1], bh[2], bh[3], BH + bRowL * 128        + ((kbyte + bKofs) ^ xm));
            LDSM_X4(bh[4], bh[5], bh[6], bh[7], BH + (bRowL + 16) * 128 + ((kbyte + bKofs) ^ xm));
            LDSM_X4(bl[0], bl[1], bl[2], bl[3], BL + bRowL * 128        + ((kbyte + bKofs) ^ xm));
            LDSM_X4(bl[4], bl[5], bl[6], bl[7], BL + (bRowL + 16) * 128 + ((kbyte + bKofs) ^ xm));
#pragma unroll
            for (int mi = 0; mi < 2; mi++)
#pragma unroll
                for (int ni = 0; ni < 4; ni++) {
                    MMA16816(acc[mi][ni], ah[mi * 4 + 0], ah[mi * 4 + 1], ah[mi * 4 + 2], ah[mi * 4 + 3],
                             bh[ni * 2 + 0], bh[ni * 2 + 1]);
                    MMA16816(acc[mi][ni], ah[mi * 4 + 0], ah[mi * 4 + 1], ah[mi * 4 + 2], ah[mi * 4 + 3],
                             bl[ni * 2 + 0], bl[ni * 2 + 1]);
                    MMA16816(acc[mi][ni], al[mi * 4 + 0], al[mi * 4 + 1], al[mi * 4 + 2], al[mi * 4 + 3],
                             bh[ni * 2 + 0], bh[ni * 2 + 1]);
                }
        }
        __syncthreads();
        if (c < NCHUNK2 - 2)
            k2_issue(sbase + (c & 1) * STAGE2, m0, n0, (c + 2) * KC2, gm);
    }

    const int g = lane >> 2, t = lane & 3;
#pragma unroll
    for (int mi = 0; mi < 2; mi++) {
#pragma unroll
        for (int ni = 0; ni < 4; ni++) {
            int mg = m0 + warpM + mi * 16 + g;
            int nc = n0 + warpN + ni * 8 + 2 * t;
            float2 bvv = *(const float2*)&b3[nc];
            float2 s0 = {acc[mi][ni][0] + bvv.x, acc[mi][ni][1] + bvv.y};
            float2 s1 = {acc[mi][ni][2] + bvv.x, acc[mi][ni][3] + bvv.y};
            *(float2*)&g_W3O[(size_t)mg * NOUT + nc] = s0;
            *(float2*)&g_W3O[(size_t)(mg + 8) * NOUT + nc] = s1;
        }
    }
}

// ---------------- K3: smem-staged coalesced logits + softmax + gather ----------------
__global__ __launch_bounds__(256) void k3(const int* __restrict__ mY,
                                          const int* __restrict__ mX,
                                          float* __restrict__ out) {
    __shared__ float so[128 * 33];           // output staging [row=b*64+c][px_local]
    __shared__ __align__(16) float lg[8][NOUT];  // per-warp logit staging (18.4KB)
    const int tid = threadIdx.x;
    const int wid = tid >> 5, lane = tid & 31;
    const int px0 = blockIdx.x * 32;

#pragma unroll 1
    for (int pi = 0; pi < 4; pi++) {
        int pxl = wid * 4 + pi;
        int px = px0 + pxl;
        int Y = mY[px], X = mX[px];

        // coalesced stage: 576 floats = 144 float4 per pixel
        {
            const float4* src4 = (const float4*)(g_W3O + (size_t)px * NOUT);
            float4* dst4 = (float4*)lg[wid];
#pragma unroll
            for (int it = 0; it < 5; it++) {
                int i = it * 32 + lane;
                if (i < 144) dst4[i] = src4[i];
            }
        }
        __syncwarp();

        // lane's 18 logits (channels 2*lane, 2*lane+1 x 9 taps) from smem
        float w[18];
        {
            const float2* l2 = (const float2*)(lg[wid] + lane * 18);
#pragma unroll
            for (int j = 0; j < 9; j++) {
                float2 v = l2[j];
                w[2 * j] = v.x; w[2 * j + 1] = v.y;
            }
        }
        __syncwarp();

        float sw0[9], sw1[9];
        float m0v = w[0], m1v = w[9];
#pragma unroll
        for (int j = 1; j < 9; j++) { m0v = fmaxf(m0v, w[j]); m1v = fmaxf(m1v, w[9 + j]); }
        float s0 = 0.f, s1 = 0.f;
#pragma unroll
        for (int j = 0; j < 9; j++) {
            sw0[j] = __expf(w[j] - m0v);     s0 += sw0[j];
            sw1[j] = __expf(w[9 + j] - m1v); s1 += sw1[j];
        }
        float inv0 = 1.f / s0, inv1 = 1.f / s1;

        float a0x = 0.f, a0y = 0.f, a1x = 0.f, a1y = 0.f;
#pragma unroll
        for (int j = 0; j < 9; j++) {
            int yy = Y + j / 3 - 1;
            int xx = X + j % 3 - 1;
            if ((unsigned)yy < HI && (unsigned)xx < WI) {
                const float* base0 = g_XT + (size_t)((0 * HI + yy) * WI + xx) * CCH + 2 * lane;
                const float* base1 = g_XT + (size_t)((1 * HI + yy) * WI + xx) * CCH + 2 * lane;
                float2 gv0 = *(const float2*)base0;
                float2 gv1 = *(const float2*)base1;
                a0x += sw0[j] * gv0.x; a0y += sw1[j] * gv0.y;
                a1x += sw0[j] * gv1.x; a1y += sw1[j] * gv1.y;
            }
        }
        so[(0 * 64 + 2 * lane    ) * 33 + pxl] = a0x * inv0;
        so[(0 * 64 + 2 * lane + 1) * 33 + pxl] = a0y * inv1;
        so[(1 * 64 + 2 * lane    ) * 33 + pxl] = a1x * inv0;
        so[(1 * 64 + 2 * lane + 1) * 33 + pxl] = a1y * inv1;
    }
    __syncthreads();

    int row = tid >> 1, half = (tid & 1) * 16;
    float* orow = out + (size_t)row * NPIX + px0 + half;
    const float* srow = so + row * 33 + half;
#pragma unroll
    for (int i = 0; i < 4; i++) {
        float4 v = {srow[4 * i], srow[4 * i + 1], srow[4 * i + 2], srow[4 * i + 3]};
        *(float4*)&orow[4 * i] = v;
    }
}

// ---------------- launch ----------------
extern "C" void kernel_launch(void* const* d_in, const int* in_sizes, int n_in,
                              void* d_out, int out_size) {
    const float* x    = (const float*)d_in[0];
    const float* pose = (const float*)d_in[1];
    const float* W1   = (const float*)d_in[2];
    const float* b1   = (const float*)d_in[3];
    const float* W2   = (const float*)d_in[4];
    const float* b2   = (const float*)d_in[5];
    const float* W3   = (const float*)d_in[6];
    const float* b3   = (const float*)d_in[7];
    const int*   mY   = (const int*)d_in[8];
    const int*   mX   = (const int*)d_in[9];
    float* out = (float*)d_out;

    cudaFuncSetAttribute(k2, cudaFuncAttributeMaxDynamicSharedMemorySize, K2_SMEM);
    cudaFuncSetAttribute(k1, cudaFuncAttributeMaxDynamicSharedMemorySize, K1_SMEM);

    prep_w<<<(NOUT * 256 + 255) / 256, 256>>>(W2, W3);
    prep_x<<<(2 * HI * WI * CCH + 255) / 256, 256>>>(x);
    dim3 g1(256 / 64, NPIX / 128);
    k1<<<g1, 256, K1_SMEM>>>(pose, W1, b1, b2);
    dim3 g2(NOUT / 64, NPIX / 128);
    k2<<<g2, 256, K2_SMEM>>>(b3);
    k3<<<NPIX / 32, 256>>>(mY, mX, out);
}

// round 9
// speedup vs baseline: 4.7533x; 1.2062x over previous
#include <cuda_runtime.h>
#include <cuda_bf16.h>
#include <cuda_fp16.h>
#include <cstdint>

#define NPIX   262144      // 512*512
#define HI     128
#define WI     128
#define CCH    64
#define NOUT   576         // C*KS*KS

// ---------------- scratch (device globals; no allocation) ----------------
__device__ __half        g_H2f[(size_t)NPIX * 256];  // fp16 relu(layer2), [pix][256]
__device__ __half        g_W3fh[NOUT * 256];         // fp16 hi of 64*W3, native [n][k]
__device__ __half        g_W3fl[NOUT * 256];         // fp16 lo residual of 64*W3
__device__ __nv_bfloat16 g_W2h[256 * 64];            // bf16 hi of W2, native [n][k]
__device__ __nv_bfloat16 g_W2l[256 * 64];            // bf16 lo residual
__device__ float g_W3O[(size_t)NPIX * NOUT];         // layer-3 logits, [pix][576]
__device__ float g_XT [2 * HI * WI * CCH];           // x transposed to [b][y][x][c]

__device__ __forceinline__ uint32_t smem_u32(const void* p) {
    uint32_t a;
    asm("{ .reg .u64 t; cvta.to.shared.u64 t, %1; cvt.u32.u64 %0, t; }" : "=r"(a) : "l"(p));
    return a;
}

#define CP16(dst, src) \
    asm volatile("cp.async.cg.shared.global [%0], [%1], 16;" :: "r"(dst), "l"(src))
#define CP_COMMIT() asm volatile("cp.async.commit_group;")
#define CP_WAITG(n) asm volatile("cp.async.wait_group %0;" :: "n"(n))

#define LDSM_X4(r0, r1, r2, r3, a) \
    asm volatile("ldmatrix.sync.aligned.m8n8.x4.shared.b16 {%0,%1,%2,%3}, [%4];" \
        : "=r"(r0), "=r"(r1), "=r"(r2), "=r"(r3) : "r"(a))

#define MMA16816BF(d, a0, a1, a2, a3, b0, b1) \
    asm volatile("mma.sync.aligned.m16n8k16.row.col.f32.bf16.bf16.f32 " \
        "{%0,%1,%2,%3}, {%4,%5,%6,%7}, {%8,%9}, {%0,%1,%2,%3};" \
        : "+f"((d)[0]), "+f"((d)[1]), "+f"((d)[2]), "+f"((d)[3]) \
        : "r"(a0), "r"(a1), "r"(a2), "r"(a3), "r"(b0), "r"(b1))

#define MMA16816F16(d, a0, a1, a2, a3, b0, b1) \
    asm volatile("mma.sync.aligned.m16n8k16.row.col.f32.f16.f16.f32 " \
        "{%0,%1,%2,%3}, {%4,%5,%6,%7}, {%8,%9}, {%0,%1,%2,%3};" \
        : "+f"((d)[0]), "+f"((d)[1]), "+f"((d)[2]), "+f"((d)[3]) \
        : "r"(a0), "r"(a1), "r"(a2), "r"(a3), "r"(b0), "r"(b1))

// ---------------- prep: weight splits ----------------
__global__ void prep_w(const float* __restrict__ W2, const float* __restrict__ W3) {
    int idx = blockIdx.x * blockDim.x + threadIdx.x;
    if (idx < 256 * 64) {            // W2 native [n][k], bf16 3-term split
        float v = W2[idx];
        __nv_bfloat16 h = __float2bfloat16(v);
        g_W2h[idx] = h;
        g_W2l[idx] = __float2bfloat16(v - __bfloat162float(h));
    }
    if (idx < NOUT * 256) {          // 64*W3 native [n][k], fp16 2-term split
        float v = W3[idx] * 64.f;
        __half h = __float2half_rn(v);
        g_W3fh[idx] = h;
        g_W3fl[idx] = __float2half_rn(v - __half2float(h));
    }
}

// ---------------- prep: x NCHW -> NHWC ----------------
__global__ void prep_x(const float* __restrict__ x) {
    int o = blockIdx.x * blockDim.x + threadIdx.x;
    if (o >= 2 * HI * WI * CCH) return;
    int c = o & 63;
    int t = o >> 6;
    int xx = t & (WI - 1); t >>= 7;
    int y  = t & (HI - 1); t >>= 7;
    int b  = t;
    g_XT[o] = x[(((b * CCH + c) * HI + y) * WI) + xx];
}

// ---------------- K1: HMMA layer-2 GEMM with inline h1 producer ----------------
#define K1_AH 0
#define K1_AL 16384
#define K1_BH 32768
#define K1_BL 40960
#define K1_SMEM 49152

__global__ __launch_bounds__(256) void k1(const float* __restrict__ pose,
                                          const float* __restrict__ W1,
                                          const float* __restrict__ b1,
                                          const float* __restrict__ b2) {
    extern __shared__ __align__(128) char sm[];
    const uint32_t sbase = smem_u32(sm);
    __shared__ float w1s[192];
    __shared__ float b1s[64];

    const int tid = threadIdx.x;
    const int wid = tid >> 5, lane = tid & 31;
    const int n0 = blockIdx.x * 64;
    const int m0 = blockIdx.y * 128;

    if (tid < 192) w1s[tid] = W1[tid];
    if (tid < 64)  b1s[tid] = b1[tid];

#pragma unroll
    for (int i = 0; i < 2; i++) {
        int o = tid + i * 256;
        int row = o >> 3, g = o & 7;
        uint32_t dst = row * 128 + ((g * 16) ^ ((row & 7) << 4));
        size_t src = (size_t)(n0 + row) * 64 + g * 8;
        CP16(sbase + K1_BH + dst, g_W2h + src);
        CP16(sbase + K1_BL + dst, g_W2l + src);
    }
    CP_COMMIT();
    __syncthreads();

    {
        int row = tid >> 1;
        int ch0 = (tid & 1) * 32;
        int px = m0 + row;
        float p0 = pose[px], p1 = pose[NPIX + px], p2 = pose[2 * NPIX + px];
#pragma unroll
        for (int g = 0; g < 4; g++) {
            __nv_bfloat16 hi8[8], lo8[8];
#pragma unroll
            for (int j = 0; j < 8; j++) {
                int c = ch0 + g * 8 + j;
                float v = fmaf(w1s[c * 3], p0,
                          fmaf(w1s[c * 3 + 1], p1,
                          fmaf(w1s[c * 3 + 2], p2, b1s[c])));
                v = fmaxf(v, 0.f);
                __nv_bfloat16 h = __float2bfloat16(v);
                hi8[j] = h;
                lo8[j] = __float2bfloat16(v - __bfloat162float(h));
            }
            int grp = ch0 / 8 + g;
            uint32_t dst = row * 128 + ((grp * 16) ^ ((row & 7) << 4));
            *(uint4*)(sm + K1_AH + dst) = *(const uint4*)hi8;
            *(uint4*)(sm + K1_AL + dst) = *(const uint4*)lo8;
        }
    }
    CP_WAITG(0);
    __syncthreads();

    const int warpM = (wid >> 1) * 32;
    const int warpN = (wid & 1) * 32;
    const int q = lane >> 3, r8 = lane & 7;
    const int xm = r8 << 4;
    const int aRowL = warpM + ((q & 1) << 3) + r8;
    const int aKofs = (q >> 1) << 4;
    const int bRowL = warpN + ((q >> 1) << 3) + r8;
    const int bKofs = (q & 1) << 4;

    const uint32_t AH = sbase + K1_AH, AL = sbase + K1_AL;
    const uint32_t BH = sbase + K1_BH, BL = sbase + K1_BL;

    float acc[2][4][4] = {};
#pragma unroll
    for (int ks = 0; ks < 4; ks++) {
        int kbyte = ks * 32;
        uint32_t ah[8], al[8], bh[8], bl[8];
        LDSM_X4(ah[0], ah[1], ah[2], ah[3], AH + aRowL * 128        + ((kbyte + aKofs) ^ xm));
        LDSM_X4(ah[4], ah[5], ah[6], ah[7], AH + (aRowL + 16) * 128 + ((kbyte + aKofs) ^ xm));
        LDSM_X4(al[0], al[1], al[2], al[3], AL + aRowL * 128        + ((kbyte + aKofs) ^ xm));
        LDSM_X4(al[4], al[5], al[6], al[7], AL + (aRowL + 16) * 128 + ((kbyte + aKofs) ^ xm));
        LDSM_X4(bh[0], bh[1], bh[2], bh[3], BH + bRowL * 128        + ((kbyte + bKofs) ^ xm));
        LDSM_X4(bh[4], bh[5], bh[6], bh[7], BH + (bRowL + 16) * 128 + ((kbyte + bKofs) ^ xm));
        LDSM_X4(bl[0], bl[1], bl[2], bl[3], BL + bRowL * 128        + ((kbyte + bKofs) ^ xm));
        LDSM_X4(bl[4], bl[5], bl[6], bl[7], BL + (bRowL + 16) * 128 + ((kbyte + bKofs) ^ xm));
#pragma unroll
        for (int mi = 0; mi < 2; mi++)
#pragma unroll
            for (int ni = 0; ni < 4; ni++) {
                MMA16816BF(acc[mi][ni], ah[mi * 4 + 0], ah[mi * 4 + 1], ah[mi * 4 + 2], ah[mi * 4 + 3],
                           bh[ni * 2 + 0], bh[ni * 2 + 1]);
                MMA16816BF(acc[mi][ni], ah[mi * 4 + 0], ah[mi * 4 + 1], ah[mi * 4 + 2], ah[mi * 4 + 3],
                           bl[ni * 2 + 0], bl[ni * 2 + 1]);
                MMA16816BF(acc[mi][ni], al[mi * 4 + 0], al[mi * 4 + 1], al[mi * 4 + 2], al[mi * 4 + 3],
                           bh[ni * 2 + 0], bh[ni * 2 + 1]);
            }
    }

    // epilogue: +b2, relu, single fp16 store
    const int g = lane >> 2, t = lane & 3;
#pragma unroll
    for (int mi = 0; mi < 2; mi++) {
#pragma unroll
        for (int ni = 0; ni < 4; ni++) {
            int nc = n0 + warpN + ni * 8 + 2 * t;
            float bv0 = b2[nc], bv1 = b2[nc + 1];
#pragma unroll
            for (int r = 0; r < 2; r++) {
                int px = m0 + warpM + mi * 16 + g + r * 8;
                float v0 = fmaxf(acc[mi][ni][2 * r + 0] + bv0, 0.f);
                float v1 = fmaxf(acc[mi][ni][2 * r + 1] + bv1, 0.f);
                __half2 hp;
                hp.x = __float2half_rn(v0);
                hp.y = __float2half_rn(v1);
                *(__half2*)&g_H2f[(size_t)px * 256 + nc] = hp;
            }
        }
    }
}

// ---------------- K2: 2-term fp16 HMMA GEMM ----------------
// W3O = (H2f * (64*W3)^T) / 64 + b3;  per chunk load A, Bh, Bl; D += A*Bh + A*Bl.
#define KC2      64
#define NCHUNK2  4
#define A_OFF    0
#define BH2_OFF  16384
#define BL2_OFF  24576
#define STAGE2   32768
#define K2_SMEM  (2 * STAGE2)     // 65536

struct K2Geom {
    int aRow[4], aDst[4], bRow[2], bDst[2], grp8;
};

__device__ __forceinline__ void k2_issue(uint32_t sb, int m0, int n0, int kb, const K2Geom& g) {
#pragma unroll
    for (int i = 0; i < 4; i++) {
        size_t asrc = (size_t)(m0 + g.aRow[i]) * 256 + kb + g.grp8;
        CP16(sb + A_OFF + g.aDst[i], g_H2f + asrc);
    }
#pragma unroll
    for (int i = 0; i < 2; i++) {
        size_t bsrc = (size_t)(n0 + g.bRow[i]) * 256 + kb + g.grp8;
        CP16(sb + BH2_OFF + g.bDst[i], g_W3fh + bsrc);
        CP16(sb + BL2_OFF + g.bDst[i], g_W3fl + bsrc);
    }
    CP_COMMIT();
}

__global__ __launch_bounds__(256, 2) void k2(const float* __restrict__ b3) {
    extern __shared__ __align__(128) char smem[];
    const uint32_t sbase = smem_u32(smem);
    const int tid = threadIdx.x;
    const int wid = tid >> 5, lane = tid & 31;

    const int n0 = blockIdx.x * 64;
    const int m0 = blockIdx.y * 128;

    K2Geom gm;
    gm.grp8 = (tid & 7) * 8;
#pragma unroll
    for (int i = 0; i < 4; i++) {
        int o = tid + i * 256;
        int row = o >> 3, grp = o & 7;
        gm.aRow[i] = row;
        gm.aDst[i] = row * 128 + ((grp * 16) ^ ((row & 7) << 4));
    }
#pragma unroll
    for (int i = 0; i < 2; i++) {
        int o = tid + i * 256;
        int row = o >> 3, grp = o & 7;
        gm.bRow[i] = row;
        gm.bDst[i] = row * 128 + ((grp * 16) ^ ((row & 7) << 4));
    }

    k2_issue(sbase + 0 * STAGE2, m0, n0, 0 * KC2, gm);
    k2_issue(sbase + 1 * STAGE2, m0, n0, 1 * KC2, gm);

    const int warpM = (wid >> 1) * 32;
    const int warpN = (wid & 1) * 32;
    const int q = lane >> 3, r8 = lane & 7;
    const int xm = r8 << 4;
    const int aRowL = warpM + ((q & 1) << 3) + r8;
    const int aKofs = (q >> 1) << 4;
    const int bRowL = warpN + ((q >> 1) << 3) + r8;
    const int bKofs = (q & 1) << 4;

    float acc[2][4][4] = {};

#pragma unroll 1
    for (int c = 0; c < NCHUNK2; c++) {
        if (c < NCHUNK2 - 1) { CP_WAITG(1); } else { CP_WAITG(0); }
        __syncthreads();

        uint32_t Sb = sbase + (c & 1) * STAGE2;
        uint32_t AA = Sb + A_OFF, BH = Sb + BH2_OFF, BL = Sb + BL2_OFF;

#pragma unroll
        for (int ks = 0; ks < 4; ks++) {
            int kbyte = ks * 32;
            uint32_t a[8], bh[8], bl[8];
            LDSM_X4(a[0], a[1], a[2], a[3], AA + aRowL * 128        + ((kbyte + aKofs) ^ xm));
            LDSM_X4(a[4], a[5], a[6], a[7], AA + (aRowL + 16) * 128 + ((kbyte + aKofs) ^ xm));
            LDSM_X4(bh[0], bh[1], bh[2], bh[3], BH + bRowL * 128        + ((kbyte + bKofs) ^ xm));
            LDSM_X4(bh[4], bh[5], bh[6], bh[7], BH + (bRowL + 16) * 128 + ((kbyte + bKofs) ^ xm));
            LDSM_X4(bl[0], bl[1], bl[2], bl[3], BL + bRowL * 128        + ((kbyte + bKofs) ^ xm));
            LDSM_X4(bl[4], bl[5], bl[6], bl[7], BL + (bRowL + 16) * 128 + ((kbyte + bKofs) ^ xm));
#pragma unroll
            for (int mi = 0; mi < 2; mi++)
#pragma unroll
                for (int ni = 0; ni < 4; ni++) {
                    MMA16816F16(acc[mi][ni], a[mi * 4 + 0], a[mi * 4 + 1], a[mi * 4 + 2], a[mi * 4 + 3],
                                bh[ni * 2 + 0], bh[ni * 2 + 1]);
                    MMA16816F16(acc[mi][ni], a[mi * 4 + 0], a[mi * 4 + 1], a[mi * 4 + 2], a[mi * 4 + 3],
                                bl[ni * 2 + 0], bl[ni * 2 + 1]);
                }
        }
        __syncthreads();
        if (c < NCHUNK2 - 2)
            k2_issue(sbase + (c & 1) * STAGE2, m0, n0, (c + 2) * KC2, gm);
    }

    const float SC = 1.f / 64.f;
    const int g = lane >> 2, t = lane & 3;
#pragma unroll
    for (int mi = 0; mi < 2; mi++) {
#pragma unroll
        for (int ni = 0; ni < 4; ni++) {
            int mg = m0 + warpM + mi * 16 + g;
            int nc = n0 + warpN + ni * 8 + 2 * t;
            float2 bvv = *(const float2*)&b3[nc];
            float2 s0 = {fmaf(acc[mi][ni][0], SC, bvv.x), fmaf(acc[mi][ni][1], SC, bvv.y)};
            float2 s1 = {fmaf(acc[mi][ni][2], SC, bvv.x), fmaf(acc[mi][ni][3], SC, bvv.y)};
            *(float2*)&g_W3O[(size_t)mg * NOUT + nc] = s0;
            *(float2*)&g_W3O[(size_t)(mg + 8) * NOUT + nc] = s1;
        }
    }
}

// ---------------- K3: smem-staged coalesced logits + softmax + gather ----------------
__global__ __launch_bounds__(256) void k3(const int* __restrict__ mY,
                                          const int* __restrict__ mX,
                                          float* __restrict__ out) {
    __shared__ float so[128 * 33];
    __shared__ __align__(16) float lg[8][NOUT];
    const int tid = threadIdx.x;
    const int wid = tid >> 5, lane = tid & 31;
    const int px0 = blockIdx.x * 32;

#pragma unroll 1
    for (int pi = 0; pi < 4; pi++) {
        int pxl = wid * 4 + pi;
        int px = px0 + pxl;
        int Y = mY[px], X = mX[px];

        {
            const float4* src4 = (const float4*)(g_W3O + (size_t)px * NOUT);
            float4* dst4 = (float4*)lg[wid];
#pragma unroll
            for (int it = 0; it < 5; it++) {
                int i = it * 32 + lane;
                if (i < 144) dst4[i] = src4[i];
            }
        }
        __syncwarp();

        float w[18];
        {
            const float2* l2 = (const float2*)(lg[wid] + lane * 18);
#pragma unroll
            for (int j = 0; j < 9; j++) {
                float2 v = l2[j];
                w[2 * j] = v.x; w[2 * j + 1] = v.y;
            }
        }
        __syncwarp();

        float sw0[9], sw1[9];
        float m0v = w[0], m1v = w[9];
#pragma unroll
        for (int j = 1; j < 9; j++) { m0v = fmaxf(m0v, w[j]); m1v = fmaxf(m1v, w[9 + j]); }
        float s0 = 0.f, s1 = 0.f;
#pragma unroll
        for (int j = 0; j < 9; j++) {
            sw0[j] = __expf(w[j] - m0v);     s0 += sw0[j];
            sw1[j] = __expf(w[9 + j] - m1v); s1 += sw1[j];
        }
        float inv0 = 1.f / s0, inv1 = 1.f / s1;

        float a0x = 0.f, a0y = 0.f, a1x = 0.f, a1y = 0.f;
#pragma unroll
        for (int j = 0; j < 9; j++) {
            int yy = Y + j / 3 - 1;
            int xx = X + j % 3 - 1;
            if ((unsigned)yy < HI && (unsigned)xx < WI) {
                const float* base0 = g_XT + (size_t)((0 * HI + yy) * WI + xx) * CCH + 2 * lane;
                const float* base1 = g_XT + (size_t)((1 * HI + yy) * WI + xx) * CCH + 2 * lane;
                float2 gv0 = *(const float2*)base0;
                float2 gv1 = *(const float2*)base1;
                a0x += sw0[j] * gv0.x; a0y += sw1[j] * gv0.y;
                a1x += sw0[j] * gv1.x; a1y += sw1[j] * gv1.y;
            }
        }
        so[(0 * 64 + 2 * lane    ) * 33 + pxl] = a0x * inv0;
        so[(0 * 64 + 2 * lane + 1) * 33 + pxl] = a0y * inv1;
        so[(1 * 64 + 2 * lane    ) * 33 + pxl] = a1x * inv0;
        so[(1 * 64 + 2 * lane + 1) * 33 + pxl] = a1y * inv1;
    }
    __syncthreads();

    int row = tid >> 1, half = (tid & 1) * 16;
    float* orow = out + (size_t)row * NPIX + px0 + half;
    const float* srow = so + row * 33 + half;
#pragma unroll
    for (int i = 0; i < 4; i++) {
        float4 v = {srow[4 * i], srow[4 * i + 1], srow[4 * i + 2], srow[4 * i + 3]};
        *(float4*)&orow[4 * i] = v;
    }
}

// ---------------- launch ----------------
extern "C" void kernel_launch(void* const* d_in, const int* in_sizes, int n_in,
                              void* d_out, int out_size) {
    const float* x    = (const float*)d_in[0];
    const float* pose = (const float*)d_in[1];
    const float* W1   = (const float*)d_in[2];
    const float* b1   = (const float*)d_in[3];
    const float* W2   = (const float*)d_in[4];
    const float* b2   = (const float*)d_in[5];
    const float* W3   = (const float*)d_in[6];
    const float* b3   = (const float*)d_in[7];
    const int*   mY   = (const int*)d_in[8];
    const int*   mX   = (const int*)d_in[9];
    float* out = (float*)d_out;

    cudaFuncSetAttribute(k2, cudaFuncAttributeMaxDynamicSharedMemorySize, K2_SMEM);
    cudaFuncSetAttribute(k1, cudaFuncAttributeMaxDynamicSharedMemorySize, K1_SMEM);

    prep_w<<<(NOUT * 256 + 255) / 256, 256>>>(W2, W3);
    prep_x<<<(2 * HI * WI * CCH + 255) / 256, 256>>>(x);
    dim3 g1(256 / 64, NPIX / 128);
    k1<<<g1, 256, K1_SMEM>>>(pose, W1, b1, b2);
    dim3 g2(NOUT / 64, NPIX / 128);
    k2<<<g2, 256, K2_SMEM>>>(b3);
    k3<<<NPIX / 32, 256>>>(mY, mX, out);
}